// round 1
// baseline (speedup 1.0000x reference)
#include <cuda_runtime.h>
#include <math.h>

// Problem constants
#define T_STEPS 256
#define BSZ     128
#define HID     512
#define MTOT    (T_STEPS * BSZ)      // 32768
#define OUT_MAIN ((size_t)T_STEPS * BSZ * HID)   // 16777216
#define STATE_N  (BSZ * HID)                     // 65536

// ---------------------------------------------------------------------------
// Device scratch (no cudaMalloc allowed)
// ---------------------------------------------------------------------------
__device__ float g_xw[4][(size_t)MTOT * HID];   // 256 MiB: x-projection + bias + theta
__device__ float g_hv[4][4][STATE_N];           // [jsplit][gate][b*512+k] partial h-proj
__device__ float g_h[STATE_N];
__device__ float g_c[STATE_N];

struct GateParams {
    const float* W[4];    // [512 x 1024] row-major; cols [0,512)=Wx, [512,1024)=Wh
    const float* b[4];    // [512]
    const float* th[4];   // [512]
};

// ---------------------------------------------------------------------------
// Phase 1: xw[g][m][n] = sum_j X[m,j] * W_g[n,j]  + b_g[n] + theta_g[n]
// M=32768, N=512 per gate, K=512.  Tiles: 128x64x16, 256 threads, 8x4/thread.
// ---------------------------------------------------------------------------
__global__ __launch_bounds__(256) void phase1_gemm(const float* __restrict__ X,
                                                   GateParams gp) {
    const int g  = blockIdx.z;
    const float* __restrict__ W = gp.W[g];
    const int m0 = blockIdx.x * 128;
    const int n0 = blockIdx.y * 64;

    __shared__ float As[16][128];
    __shared__ float Bs[16][68];   // +4 pad

    const int tid = threadIdx.x;
    const int tx = tid & 15, ty = tid >> 4;

    float acc[8][4];
#pragma unroll
    for (int i = 0; i < 8; i++)
#pragma unroll
        for (int j = 0; j < 4; j++) acc[i][j] = 0.f;

    for (int k0 = 0; k0 < 512; k0 += 16) {
#pragma unroll
        for (int i = 0; i < 2; i++) {
            int f = tid * 2 + i;            // 0..511
            int row = f >> 2, kk = (f & 3) << 2;
            float4 v = *reinterpret_cast<const float4*>(
                X + (size_t)(m0 + row) * 512 + k0 + kk);
            As[kk + 0][row] = v.x; As[kk + 1][row] = v.y;
            As[kk + 2][row] = v.z; As[kk + 3][row] = v.w;
        }
        {
            int row = tid >> 2, kk = (tid & 3) << 2;
            float4 v = *reinterpret_cast<const float4*>(
                W + (size_t)(n0 + row) * 1024 + k0 + kk);
            Bs[kk + 0][row] = v.x; Bs[kk + 1][row] = v.y;
            Bs[kk + 2][row] = v.z; Bs[kk + 3][row] = v.w;
        }
        __syncthreads();
#pragma unroll
        for (int kk = 0; kk < 16; kk++) {
            float a[8], bb[4];
#pragma unroll
            for (int i = 0; i < 8; i++) a[i] = As[kk][ty * 8 + i];
#pragma unroll
            for (int j = 0; j < 4; j++) bb[j] = Bs[kk][tx * 4 + j];
#pragma unroll
            for (int i = 0; i < 8; i++)
#pragma unroll
                for (int j = 0; j < 4; j++) acc[i][j] += a[i] * bb[j];
        }
        __syncthreads();
    }

    const float* __restrict__ bias = gp.b[g];
    const float* __restrict__ th   = gp.th[g];
    const int n = n0 + tx * 4;
    float4 addv;
    addv.x = bias[n + 0] + th[n + 0];
    addv.y = bias[n + 1] + th[n + 1];
    addv.z = bias[n + 2] + th[n + 2];
    addv.w = bias[n + 3] + th[n + 3];
#pragma unroll
    for (int i = 0; i < 8; i++) {
        int m = m0 + ty * 8 + i;
        float4 o;
        o.x = acc[i][0] + addv.x; o.y = acc[i][1] + addv.y;
        o.z = acc[i][2] + addv.z; o.w = acc[i][3] + addv.w;
        *reinterpret_cast<float4*>(&g_xw[g][(size_t)m * 512 + n]) = o;
    }
}

// ---------------------------------------------------------------------------
// Per-step recurrent GEMM: hv[js][g][b][k] = sum_{j in js-chunk} h[b,j]*Wh_g[k,j]
// M=128(b), N=64 k-tile, K-chunk=128 (js in 0..3).  grid(8 ktiles, 4 gates, 4 js)
// ---------------------------------------------------------------------------
__global__ __launch_bounds__(256) void step_gemm(GateParams gp) {
    const int g  = blockIdx.y;
    const int js = blockIdx.z;
    const float* __restrict__ W = gp.W[g];
    const int n0 = blockIdx.x * 64;
    const int jA = js * 128;        // column offset into h
    const int jW = 512 + js * 128;  // column offset into W (Wh part)

    __shared__ float As[16][128];
    __shared__ float Bs[16][68];

    const int tid = threadIdx.x;
    const int tx = tid & 15, ty = tid >> 4;

    float acc[8][4];
#pragma unroll
    for (int i = 0; i < 8; i++)
#pragma unroll
        for (int j = 0; j < 4; j++) acc[i][j] = 0.f;

    for (int k0 = 0; k0 < 128; k0 += 16) {
#pragma unroll
        for (int i = 0; i < 2; i++) {
            int f = tid * 2 + i;
            int row = f >> 2, kk = (f & 3) << 2;
            float4 v = *reinterpret_cast<const float4*>(
                g_h + (size_t)row * 512 + jA + k0 + kk);
            As[kk + 0][row] = v.x; As[kk + 1][row] = v.y;
            As[kk + 2][row] = v.z; As[kk + 3][row] = v.w;
        }
        {
            int row = tid >> 2, kk = (tid & 3) << 2;
            float4 v = *reinterpret_cast<const float4*>(
                W + (size_t)(n0 + row) * 1024 + jW + k0 + kk);
            Bs[kk + 0][row] = v.x; Bs[kk + 1][row] = v.y;
            Bs[kk + 2][row] = v.z; Bs[kk + 3][row] = v.w;
        }
        __syncthreads();
#pragma unroll
        for (int kk = 0; kk < 16; kk++) {
            float a[8], bb[4];
#pragma unroll
            for (int i = 0; i < 8; i++) a[i] = As[kk][ty * 8 + i];
#pragma unroll
            for (int j = 0; j < 4; j++) bb[j] = Bs[kk][tx * 4 + j];
#pragma unroll
            for (int i = 0; i < 8; i++)
#pragma unroll
                for (int j = 0; j < 4; j++) acc[i][j] += a[i] * bb[j];
        }
        __syncthreads();
    }

    const int n = n0 + tx * 4;
#pragma unroll
    for (int i = 0; i < 8; i++) {
        int m = ty * 8 + i;   // batch row
        float4 o;
        o.x = acc[i][0]; o.y = acc[i][1]; o.z = acc[i][2]; o.w = acc[i][3];
        *reinterpret_cast<float4*>(&g_hv[js][g][(size_t)m * 512 + n]) = o;
    }
}

// ---------------------------------------------------------------------------
// Per-step scan + gates: one CTA per batch row, 512 threads (one per k).
//   v   = xw (already has b+theta) + sum_js hv
//   u   = cos(v);  p = inclusive cumprod over k  (warp shfl scan + warp fixup)
//   f,i = sigmoid; g = tanh; o = sigmoid;  c = f*c + i*g;  h = o*tanh(c)
// ---------------------------------------------------------------------------
__device__ __forceinline__ float sigmoidf_(float x) {
    return 1.0f / (1.0f + expf(-x));
}

__global__ __launch_bounds__(512) void step_scan(float* __restrict__ out, int t) {
    const int b = blockIdx.x;
    const int k = threadIdx.x;
    const int lane = k & 31;
    const int warp = k >> 5;

    float u[4];
    const size_t row = ((size_t)t * BSZ + b) * 512 + k;
    const int idx = b * 512 + k;
#pragma unroll
    for (int g = 0; g < 4; g++) {
        float v = g_xw[g][row];
#pragma unroll
        for (int js = 0; js < 4; js++) v += g_hv[js][g][idx];
        u[g] = cosf(v);
    }

    // warp-level inclusive product scan (4 gates in lockstep)
#pragma unroll
    for (int o = 1; o < 32; o <<= 1) {
#pragma unroll
        for (int g = 0; g < 4; g++) {
            float up = __shfl_up_sync(0xffffffffu, u[g], o);
            if (lane >= o) u[g] *= up;
        }
    }

    __shared__ float wt[16][4];
    if (lane == 31) {
#pragma unroll
        for (int g = 0; g < 4; g++) wt[warp][g] = u[g];
    }
    __syncthreads();

    float pre[4] = {1.f, 1.f, 1.f, 1.f};
    for (int w = 0; w < warp; w++) {
#pragma unroll
        for (int g = 0; g < 4; g++) pre[g] *= wt[w][g];
    }
#pragma unroll
    for (int g = 0; g < 4; g++) u[g] *= pre[g];

    const float f  = sigmoidf_(u[0]);
    const float ii = sigmoidf_(u[1]);
    const float gg = tanhf(u[2]);
    const float oo = sigmoidf_(u[3]);

    const float c = f * g_c[idx] + ii * gg;
    const float h = oo * tanhf(c);

    g_c[idx] = c;
    g_h[idx] = h;
    out[(size_t)t * STATE_N + idx] = h;   // outputs[t]
    out[OUT_MAIN + idx]            = h;   // hx (final overwrite wins)
    out[OUT_MAIN + STATE_N + idx]  = c;   // cx
}

// ---------------------------------------------------------------------------
__global__ void init_state() {
    int i = blockIdx.x * blockDim.x + threadIdx.x;
    if (i < STATE_N) { g_h[i] = 0.f; g_c[i] = 0.f; }
}

// ---------------------------------------------------------------------------
extern "C" void kernel_launch(void* const* d_in, const int* in_sizes, int n_in,
                              void* d_out, int out_size) {
    const float* X = (const float*)d_in[0];
    GateParams gp;
    for (int g = 0; g < 4; g++) {
        gp.W[g]  = (const float*)d_in[1 + 3 * g];
        gp.b[g]  = (const float*)d_in[2 + 3 * g];
        gp.th[g] = (const float*)d_in[3 + 3 * g];
    }
    float* out = (float*)d_out;

    init_state<<<(STATE_N + 255) / 256, 256>>>();

    // Phase 1: x-projection for all timesteps/gates (parallel)
    dim3 g1(MTOT / 128, HID / 64, 4);
    phase1_gemm<<<g1, 256>>>(X, gp);

    // Recurrence
    for (int t = 0; t < T_STEPS; t++) {
        step_gemm<<<dim3(8, 4, 4), 256>>>(gp);
        step_scan<<<BSZ, 512>>>(out, t);
    }
}

// round 3
// speedup vs baseline: 1.7149x; 1.7149x over previous
#include <cuda_runtime.h>
#include <cuda_bf16.h>
#include <mma.h>
#include <math.h>
#include <stdint.h>

using namespace nvcuda;

// Problem constants
#define T_STEPS 256
#define BSZ     128
#define HID     512
#define MTOT    (T_STEPS * BSZ)                  // 32768
#define OUT_MAIN ((size_t)T_STEPS * BSZ * HID)   // 16777216
#define STATE_N  (BSZ * HID)                     // 65536

// ---------------------------------------------------------------------------
// Device scratch
// ---------------------------------------------------------------------------
__device__ __align__(256) float g_xw[4][(size_t)MTOT * HID];   // 256 MiB
__device__ __align__(256) float g_hv[4][4][STATE_N];           // [js][gate]
__device__ __align__(256) float g_c[STATE_N];
__device__ __align__(256) __nv_bfloat16 g_h_h[STATE_N];
__device__ __align__(256) __nv_bfloat16 g_h_l[STATE_N];

__device__ __align__(256) __nv_bfloat16 g_Xh[(size_t)MTOT * 512];
__device__ __align__(256) __nv_bfloat16 g_Xl[(size_t)MTOT * 512];
__device__ __align__(256) __nv_bfloat16 g_Wxh[4][512 * 512];
__device__ __align__(256) __nv_bfloat16 g_Wxl[4][512 * 512];
__device__ __align__(256) __nv_bfloat16 g_Whh[4][512 * 512];
__device__ __align__(256) __nv_bfloat16 g_Whl[4][512 * 512];
__device__ __align__(256) float g_badd[4][512];

struct GateParams {
    const float* W[4];    // [512 x 1024]; cols [0,512)=Wx, [512,1024)=Wh
    const float* b[4];
    const float* th[4];
};

// ---------------------------------------------------------------------------
// fp32 -> bf16 hi/lo split
// ---------------------------------------------------------------------------
__device__ __forceinline__ void split_bf16(float x, __nv_bfloat16& h, __nv_bfloat16& l) {
    h = __float2bfloat16_rn(x);
    l = __float2bfloat16_rn(x - __bfloat162float(h));
}

__global__ __launch_bounds__(256) void convert_x(const float* __restrict__ X) {
    size_t i = ((size_t)blockIdx.x * blockDim.x + threadIdx.x) * 2;
    float2 v = *reinterpret_cast<const float2*>(X + i);
    __nv_bfloat16 h0, l0, h1, l1;
    split_bf16(v.x, h0, l0); split_bf16(v.y, h1, l1);
    *reinterpret_cast<__nv_bfloat162*>(&g_Xh[i]) = __nv_bfloat162(h0, h1);
    *reinterpret_cast<__nv_bfloat162*>(&g_Xl[i]) = __nv_bfloat162(l0, l1);
}

// covers all 4 gates x 512 rows x 1024 cols (Wx and Wh halves)
__global__ __launch_bounds__(256) void convert_w(GateParams gp) {
    size_t i = ((size_t)blockIdx.x * blockDim.x + threadIdx.x) * 2;
    int g = (int)(i >> 19);          // 512*1024 per gate
    size_t r = i & 524287;
    int n = (int)(r >> 10), k = (int)(r & 1023);
    float2 v = *reinterpret_cast<const float2*>(gp.W[g] + (size_t)n * 1024 + k);
    __nv_bfloat16 h0, l0, h1, l1;
    split_bf16(v.x, h0, l0); split_bf16(v.y, h1, l1);
    if (k < 512) {
        size_t d = (size_t)n * 512 + k;
        *reinterpret_cast<__nv_bfloat162*>(&g_Wxh[g][d]) = __nv_bfloat162(h0, h1);
        *reinterpret_cast<__nv_bfloat162*>(&g_Wxl[g][d]) = __nv_bfloat162(l0, l1);
    } else {
        size_t d = (size_t)n * 512 + (k - 512);
        *reinterpret_cast<__nv_bfloat162*>(&g_Whh[g][d]) = __nv_bfloat162(h0, h1);
        *reinterpret_cast<__nv_bfloat162*>(&g_Whl[g][d]) = __nv_bfloat162(l0, l1);
    }
}

__global__ void make_badd(GateParams gp) {
    int i = blockIdx.x * blockDim.x + threadIdx.x;
    int g = i >> 9, n = i & 511;
    g_badd[g][n] = gp.b[g][n] + gp.th[g][n];
}

// ===========================================================================
// Phase 1 via WMMA bf16 3-pass: xw[g][m][n] = X[m,:] . Wx_g[n,:] (+b+theta)
// CTA tile 128(m) x 128(n), K-chunks of 32.  8 warps = 4(m) x 2(n),
// warp tile 32 x 64 = 2 x 4 wmma(16x16) accumulators.
// smem: Ah|Al|Bh|Bl each 128 x 40(stride) bf16 = 40KB total.
// grid: x = 16 (gate*ntile, inner -> W stays L2 resident), y = 256 (mtile)
// ===========================================================================
#define SSTR 40   // smem K-stride (32 data + 8 pad), 80B rows: 16B-aligned

__global__ __launch_bounds__(256) void phase1_wmma() {
    __shared__ __align__(16) __nv_bfloat16 sm[4 * 128 * SSTR];  // 40960 B
    __nv_bfloat16* sAh = sm;
    __nv_bfloat16* sAl = sm + 128 * SSTR;
    __nv_bfloat16* sBh = sm + 2 * 128 * SSTR;
    __nv_bfloat16* sBl = sm + 3 * 128 * SSTR;

    const int tid = threadIdx.x, wid = tid >> 5;
    const int nt = blockIdx.x;            // 0..15
    const int g  = nt >> 2;
    const int n0 = (nt & 3) * 128;
    const int m0 = blockIdx.y * 128;
    const int wm = wid >> 1;              // 0..3
    const int wn = wid & 1;               // 0..1

    wmma::fragment<wmma::accumulator, 16, 16, 16, float> acc[2][4];
#pragma unroll
    for (int i = 0; i < 2; i++)
#pragma unroll
        for (int j = 0; j < 4; j++) wmma::fill_fragment(acc[i][j], 0.0f);

    for (int k0 = 0; k0 < 512; k0 += 32) {
        // stage: 4 matrices x 128 rows x 32 bf16 (= 4 uint4/row)
#pragma unroll
        for (int it = 0; it < 2; it++) {
            int i = tid + it * 256;       // 0..511
            int r = i >> 2, c = (i & 3) * 8;
            size_t sA = (size_t)(m0 + r) * 512 + k0 + c;
            size_t sB = (size_t)(n0 + r) * 512 + k0 + c;
            int d = r * SSTR + c;
            *reinterpret_cast<uint4*>(&sAh[d]) = *reinterpret_cast<const uint4*>(&g_Xh[sA]);
            *reinterpret_cast<uint4*>(&sAl[d]) = *reinterpret_cast<const uint4*>(&g_Xl[sA]);
            *reinterpret_cast<uint4*>(&sBh[d]) = *reinterpret_cast<const uint4*>(&g_Wxh[g][sB]);
            *reinterpret_cast<uint4*>(&sBl[d]) = *reinterpret_cast<const uint4*>(&g_Wxl[g][sB]);
        }
        __syncthreads();

#pragma unroll
        for (int kk = 0; kk < 32; kk += 16) {
            wmma::fragment<wmma::matrix_a, 16, 16, 16, __nv_bfloat16, wmma::row_major> ah[2], al[2];
            wmma::fragment<wmma::matrix_b, 16, 16, 16, __nv_bfloat16, wmma::col_major> bh[4], bl[4];
#pragma unroll
            for (int i = 0; i < 2; i++) {
                int row = wm * 32 + i * 16;
                wmma::load_matrix_sync(ah[i], &sAh[row * SSTR + kk], SSTR);
                wmma::load_matrix_sync(al[i], &sAl[row * SSTR + kk], SSTR);
            }
#pragma unroll
            for (int j = 0; j < 4; j++) {
                int row = wn * 64 + j * 16;
                wmma::load_matrix_sync(bh[j], &sBh[row * SSTR + kk], SSTR);
                wmma::load_matrix_sync(bl[j], &sBl[row * SSTR + kk], SSTR);
            }
#pragma unroll
            for (int i = 0; i < 2; i++)
#pragma unroll
                for (int j = 0; j < 4; j++) {
                    wmma::mma_sync(acc[i][j], ah[i], bh[j], acc[i][j]);
                    wmma::mma_sync(acc[i][j], ah[i], bl[j], acc[i][j]);
                    wmma::mma_sync(acc[i][j], al[i], bh[j], acc[i][j]);
                }
        }
        __syncthreads();
    }

    // Epilogue: two n-halves of 64 cols through smem (128 x 68 floats = 34.8KB)
    float* smf = reinterpret_cast<float*>(sm);
    const float* __restrict__ badd = g_badd[g];
#pragma unroll
    for (int half = 0; half < 2; half++) {
        if (wn == half) {
#pragma unroll
            for (int i = 0; i < 2; i++)
#pragma unroll
                for (int j = 0; j < 4; j++)
                    wmma::store_matrix_sync(&smf[(wm * 32 + i * 16) * 68 + j * 16],
                                            acc[i][j], 68, wmma::mem_row_major);
        }
        __syncthreads();
#pragma unroll
        for (int it = 0; it < 8; it++) {
            int i = tid + it * 256;          // 0..2047
            int r = i >> 4, c = (i & 15) * 4;
            int n = n0 + half * 64 + c;
            float4 v = *reinterpret_cast<const float4*>(&smf[r * 68 + c]);
            v.x += badd[n + 0]; v.y += badd[n + 1];
            v.z += badd[n + 2]; v.w += badd[n + 3];
            *reinterpret_cast<float4*>(&g_xw[g][(size_t)(m0 + r) * 512 + n]) = v;
        }
        __syncthreads();
    }
}

// ===========================================================================
// Step GEMM via WMMA: hv[js][g][b][n] = sum_{k in js chunk} h[b,k]*Wh_g[n,k]
// CTA tile 128(m=batch) x 64(n), K=128 per js in chunks of 32.
// 8 warps = 4(m) x 2(n), warp tile 32 x 32 = 2 x 2 accumulators.
// grid (8 ntiles, 4 gates, 4 js) = 128 CTAs.
// ===========================================================================
__global__ __launch_bounds__(256) void step_gemm_wmma() {
    __shared__ __align__(16) __nv_bfloat16 sm[2 * 128 * SSTR + 2 * 64 * SSTR]; // 30KB
    __nv_bfloat16* sAh = sm;
    __nv_bfloat16* sAl = sm + 128 * SSTR;
    __nv_bfloat16* sBh = sm + 2 * 128 * SSTR;
    __nv_bfloat16* sBl = sm + 2 * 128 * SSTR + 64 * SSTR;

    const int tid = threadIdx.x, wid = tid >> 5;
    const int n0 = blockIdx.x * 64;
    const int g  = blockIdx.y;
    const int js = blockIdx.z;
    const int kbase = js * 128;
    const int wm = wid >> 1;
    const int wn = wid & 1;

    wmma::fragment<wmma::accumulator, 16, 16, 16, float> acc[2][2];
#pragma unroll
    for (int i = 0; i < 2; i++)
#pragma unroll
        for (int j = 0; j < 2; j++) wmma::fill_fragment(acc[i][j], 0.0f);

    for (int k0 = 0; k0 < 128; k0 += 32) {
        // A: 128 rows x 32 = 512 uint4; B: 64 rows x 32 = 256 uint4
#pragma unroll
        for (int it = 0; it < 2; it++) {
            int i = tid + it * 256;
            int r = i >> 2, c = (i & 3) * 8;
            size_t sA = (size_t)r * 512 + kbase + k0 + c;
            int d = r * SSTR + c;
            *reinterpret_cast<uint4*>(&sAh[d]) = *reinterpret_cast<const uint4*>(&g_h_h[sA]);
            *reinterpret_cast<uint4*>(&sAl[d]) = *reinterpret_cast<const uint4*>(&g_h_l[sA]);
        }
        if (tid < 256) {
            int r = tid >> 2, c = (tid & 3) * 8;
            size_t sB = (size_t)(n0 + r) * 512 + kbase + k0 + c;
            int d = r * SSTR + c;
            if (r < 64) {
                *reinterpret_cast<uint4*>(&sBh[d]) = *reinterpret_cast<const uint4*>(&g_Whh[g][sB]);
                *reinterpret_cast<uint4*>(&sBl[d]) = *reinterpret_cast<const uint4*>(&g_Whl[g][sB]);
            }
        }
        __syncthreads();

#pragma unroll
        for (int kk = 0; kk < 32; kk += 16) {
            wmma::fragment<wmma::matrix_a, 16, 16, 16, __nv_bfloat16, wmma::row_major> ah[2], al[2];
            wmma::fragment<wmma::matrix_b, 16, 16, 16, __nv_bfloat16, wmma::col_major> bh[2], bl[2];
#pragma unroll
            for (int i = 0; i < 2; i++) {
                int row = wm * 32 + i * 16;
                wmma::load_matrix_sync(ah[i], &sAh[row * SSTR + kk], SSTR);
                wmma::load_matrix_sync(al[i], &sAl[row * SSTR + kk], SSTR);
            }
#pragma unroll
            for (int j = 0; j < 2; j++) {
                int row = wn * 32 + j * 16;
                wmma::load_matrix_sync(bh[j], &sBh[row * SSTR + kk], SSTR);
                wmma::load_matrix_sync(bl[j], &sBl[row * SSTR + kk], SSTR);
            }
#pragma unroll
            for (int i = 0; i < 2; i++)
#pragma unroll
                for (int j = 0; j < 2; j++) {
                    wmma::mma_sync(acc[i][j], ah[i], bh[j], acc[i][j]);
                    wmma::mma_sync(acc[i][j], ah[i], bl[j], acc[i][j]);
                    wmma::mma_sync(acc[i][j], al[i], bh[j], acc[i][j]);
                }
        }
        __syncthreads();
    }

    // store directly to g_hv (row-major, ldm 512)
    float* dst = g_hv[js][g];
#pragma unroll
    for (int i = 0; i < 2; i++)
#pragma unroll
        for (int j = 0; j < 2; j++) {
            int m = wm * 32 + i * 16;
            int n = n0 + wn * 32 + j * 16;
            wmma::store_matrix_sync(&dst[(size_t)m * 512 + n], acc[i][j], 512,
                                    wmma::mem_row_major);
        }
}

// ===========================================================================
// Per-step scan + gates (one CTA per batch row, 512 threads)
// ===========================================================================
__device__ __forceinline__ float sigmoidf_(float x) {
    return 1.0f / (1.0f + expf(-x));
}

__global__ __launch_bounds__(512) void step_scan(float* __restrict__ out, int t) {
    const int b = blockIdx.x;
    const int k = threadIdx.x;
    const int lane = k & 31;
    const int warp = k >> 5;

    float u[4];
    const size_t row = ((size_t)t * BSZ + b) * 512 + k;
    const int idx = b * 512 + k;
#pragma unroll
    for (int g = 0; g < 4; g++) {
        float v = g_xw[g][row];
#pragma unroll
        for (int js = 0; js < 4; js++) v += g_hv[js][g][idx];
        u[g] = cosf(v);
    }

#pragma unroll
    for (int o = 1; o < 32; o <<= 1) {
#pragma unroll
        for (int g = 0; g < 4; g++) {
            float up = __shfl_up_sync(0xffffffffu, u[g], o);
            if (lane >= o) u[g] *= up;
        }
    }

    __shared__ float wt[16][4];
    if (lane == 31) {
#pragma unroll
        for (int g = 0; g < 4; g++) wt[warp][g] = u[g];
    }
    __syncthreads();

    float pre[4] = {1.f, 1.f, 1.f, 1.f};
    for (int w = 0; w < warp; w++) {
#pragma unroll
        for (int g = 0; g < 4; g++) pre[g] *= wt[w][g];
    }
#pragma unroll
    for (int g = 0; g < 4; g++) u[g] *= pre[g];

    const float f  = sigmoidf_(u[0]);
    const float ii = sigmoidf_(u[1]);
    const float gg = tanhf(u[2]);
    const float oo = sigmoidf_(u[3]);

    const float c = f * g_c[idx] + ii * gg;
    const float h = oo * tanhf(c);

    g_c[idx] = c;
    __nv_bfloat16 hh, hl;
    split_bf16(h, hh, hl);
    g_h_h[idx] = hh;
    g_h_l[idx] = hl;

    out[(size_t)t * STATE_N + idx] = h;
    if (t == T_STEPS - 1) {
        out[OUT_MAIN + idx]           = h;
        out[OUT_MAIN + STATE_N + idx] = c;
    }
}

__global__ void init_state() {
    int i = blockIdx.x * blockDim.x + threadIdx.x;
    if (i < STATE_N) {
        g_c[i] = 0.f;
        g_h_h[i] = __float2bfloat16(0.f);
        g_h_l[i] = __float2bfloat16(0.f);
    }
}

// ===========================================================================
extern "C" void kernel_launch(void* const* d_in, const int* in_sizes, int n_in,
                              void* d_out, int out_size) {
    const float* X = (const float*)d_in[0];
    GateParams gp;
    for (int g = 0; g < 4; g++) {
        gp.W[g]  = (const float*)d_in[1 + 3 * g];
        gp.b[g]  = (const float*)d_in[2 + 3 * g];
        gp.th[g] = (const float*)d_in[3 + 3 * g];
    }
    float* out = (float*)d_out;

    init_state<<<(STATE_N + 255) / 256, 256>>>();

    // bf16 hi/lo conversion
    convert_x<<<(MTOT * 512 / 2) / 256, 256>>>(X);
    convert_w<<<(4 * 512 * 1024 / 2) / 256, 256>>>(gp);
    make_badd<<<8, 256>>>(gp);

    // Phase 1 on tensor cores (legacy HMMA path)
    phase1_wmma<<<dim3(16, MTOT / 128), 256>>>();

    // Recurrence
    for (int t = 0; t < T_STEPS; t++) {
        step_gemm_wmma<<<dim3(8, 4, 4), 256>>>();
        step_scan<<<BSZ, 512>>>(out, t);
    }
}

// round 4
// speedup vs baseline: 1.7414x; 1.0155x over previous
#include <cuda_runtime.h>
#include <cuda_bf16.h>
#include <mma.h>
#include <math.h>
#include <stdint.h>

using namespace nvcuda;

// Problem constants
#define T_STEPS 256
#define BSZ     128
#define HID     512
#define MTOT    (T_STEPS * BSZ)                  // 32768
#define OUT_MAIN ((size_t)T_STEPS * BSZ * HID)   // 16777216
#define STATE_N  (BSZ * HID)                     // 65536

// ---------------------------------------------------------------------------
// Device scratch
// ---------------------------------------------------------------------------
__device__ __align__(256) float g_xw[4][(size_t)MTOT * HID];   // 256 MiB
__device__ __align__(256) float g_hv[4][4][STATE_N];           // [js][gate]
__device__ __align__(256) float g_c[STATE_N];
__device__ __align__(256) __nv_bfloat16 g_h_h[STATE_N];
__device__ __align__(256) __nv_bfloat16 g_h_l[STATE_N];

__device__ __align__(256) __nv_bfloat16 g_Xh[(size_t)MTOT * 512];
__device__ __align__(256) __nv_bfloat16 g_Xl[(size_t)MTOT * 512];
__device__ __align__(256) __nv_bfloat16 g_Wxh[4][512 * 512];
__device__ __align__(256) __nv_bfloat16 g_Wxl[4][512 * 512];
__device__ __align__(256) __nv_bfloat16 g_Whh[4][512 * 512];
__device__ __align__(256) __nv_bfloat16 g_Whl[4][512 * 512];
__device__ __align__(256) float g_badd[4][512];
__device__ unsigned g_barrier;

struct GateParams {
    const float* W[4];    // [512 x 1024]; cols [0,512)=Wx, [512,1024)=Wh
    const float* b[4];
    const float* th[4];
};

// ---------------------------------------------------------------------------
// fp32 -> bf16 hi/lo split
// ---------------------------------------------------------------------------
__device__ __forceinline__ void split_bf16(float x, __nv_bfloat16& h, __nv_bfloat16& l) {
    h = __float2bfloat16_rn(x);
    l = __float2bfloat16_rn(x - __bfloat162float(h));
}

__global__ __launch_bounds__(256) void convert_x(const float* __restrict__ X) {
    size_t i = ((size_t)blockIdx.x * blockDim.x + threadIdx.x) * 2;
    float2 v = *reinterpret_cast<const float2*>(X + i);
    __nv_bfloat16 h0, l0, h1, l1;
    split_bf16(v.x, h0, l0); split_bf16(v.y, h1, l1);
    *reinterpret_cast<__nv_bfloat162*>(&g_Xh[i]) = __nv_bfloat162(h0, h1);
    *reinterpret_cast<__nv_bfloat162*>(&g_Xl[i]) = __nv_bfloat162(l0, l1);
}

__global__ __launch_bounds__(256) void convert_w(GateParams gp) {
    size_t i = ((size_t)blockIdx.x * blockDim.x + threadIdx.x) * 2;
    int g = (int)(i >> 19);          // 512*1024 per gate
    size_t r = i & 524287;
    int n = (int)(r >> 10), k = (int)(r & 1023);
    float2 v = *reinterpret_cast<const float2*>(gp.W[g] + (size_t)n * 1024 + k);
    __nv_bfloat16 h0, l0, h1, l1;
    split_bf16(v.x, h0, l0); split_bf16(v.y, h1, l1);
    if (k < 512) {
        size_t d = (size_t)n * 512 + k;
        *reinterpret_cast<__nv_bfloat162*>(&g_Wxh[g][d]) = __nv_bfloat162(h0, h1);
        *reinterpret_cast<__nv_bfloat162*>(&g_Wxl[g][d]) = __nv_bfloat162(l0, l1);
    } else {
        size_t d = (size_t)n * 512 + (k - 512);
        *reinterpret_cast<__nv_bfloat162*>(&g_Whh[g][d]) = __nv_bfloat162(h0, h1);
        *reinterpret_cast<__nv_bfloat162*>(&g_Whl[g][d]) = __nv_bfloat162(l0, l1);
    }
}

__global__ void make_badd(GateParams gp) {
    int i = blockIdx.x * blockDim.x + threadIdx.x;
    int g = i >> 9, n = i & 511;
    g_badd[g][n] = gp.b[g][n] + gp.th[g][n];
}

// ===========================================================================
// Phase 1 via WMMA bf16 3-pass (at legacy-HMMA roofline, unchanged)
// ===========================================================================
#define SSTR 40

__global__ __launch_bounds__(256) void phase1_wmma() {
    __shared__ __align__(16) __nv_bfloat16 sm[4 * 128 * SSTR];
    __nv_bfloat16* sAh = sm;
    __nv_bfloat16* sAl = sm + 128 * SSTR;
    __nv_bfloat16* sBh = sm + 2 * 128 * SSTR;
    __nv_bfloat16* sBl = sm + 3 * 128 * SSTR;

    const int tid = threadIdx.x, wid = tid >> 5;
    const int nt = blockIdx.x;
    const int g  = nt >> 2;
    const int n0 = (nt & 3) * 128;
    const int m0 = blockIdx.y * 128;
    const int wm = wid >> 1;
    const int wn = wid & 1;

    wmma::fragment<wmma::accumulator, 16, 16, 16, float> acc[2][4];
#pragma unroll
    for (int i = 0; i < 2; i++)
#pragma unroll
        for (int j = 0; j < 4; j++) wmma::fill_fragment(acc[i][j], 0.0f);

    for (int k0 = 0; k0 < 512; k0 += 32) {
#pragma unroll
        for (int it = 0; it < 2; it++) {
            int i = tid + it * 256;
            int r = i >> 2, c = (i & 3) * 8;
            size_t sA = (size_t)(m0 + r) * 512 + k0 + c;
            size_t sB = (size_t)(n0 + r) * 512 + k0 + c;
            int d = r * SSTR + c;
            *reinterpret_cast<uint4*>(&sAh[d]) = *reinterpret_cast<const uint4*>(&g_Xh[sA]);
            *reinterpret_cast<uint4*>(&sAl[d]) = *reinterpret_cast<const uint4*>(&g_Xl[sA]);
            *reinterpret_cast<uint4*>(&sBh[d]) = *reinterpret_cast<const uint4*>(&g_Wxh[g][sB]);
            *reinterpret_cast<uint4*>(&sBl[d]) = *reinterpret_cast<const uint4*>(&g_Wxl[g][sB]);
        }
        __syncthreads();

#pragma unroll
        for (int kk = 0; kk < 32; kk += 16) {
            wmma::fragment<wmma::matrix_a, 16, 16, 16, __nv_bfloat16, wmma::row_major> ah[2], al[2];
            wmma::fragment<wmma::matrix_b, 16, 16, 16, __nv_bfloat16, wmma::col_major> bh[4], bl[4];
#pragma unroll
            for (int i = 0; i < 2; i++) {
                int row = wm * 32 + i * 16;
                wmma::load_matrix_sync(ah[i], &sAh[row * SSTR + kk], SSTR);
                wmma::load_matrix_sync(al[i], &sAl[row * SSTR + kk], SSTR);
            }
#pragma unroll
            for (int j = 0; j < 4; j++) {
                int row = wn * 64 + j * 16;
                wmma::load_matrix_sync(bh[j], &sBh[row * SSTR + kk], SSTR);
                wmma::load_matrix_sync(bl[j], &sBl[row * SSTR + kk], SSTR);
            }
#pragma unroll
            for (int i = 0; i < 2; i++)
#pragma unroll
                for (int j = 0; j < 4; j++) {
                    wmma::mma_sync(acc[i][j], ah[i], bh[j], acc[i][j]);
                    wmma::mma_sync(acc[i][j], ah[i], bl[j], acc[i][j]);
                    wmma::mma_sync(acc[i][j], al[i], bh[j], acc[i][j]);
                }
        }
        __syncthreads();
    }

    float* smf = reinterpret_cast<float*>(sm);
    const float* __restrict__ badd = g_badd[g];
#pragma unroll
    for (int half = 0; half < 2; half++) {
        if (wn == half) {
#pragma unroll
            for (int i = 0; i < 2; i++)
#pragma unroll
                for (int j = 0; j < 4; j++)
                    wmma::store_matrix_sync(&smf[(wm * 32 + i * 16) * 68 + j * 16],
                                            acc[i][j], 68, wmma::mem_row_major);
        }
        __syncthreads();
#pragma unroll
        for (int it = 0; it < 8; it++) {
            int i = tid + it * 256;
            int r = i >> 4, c = (i & 15) * 4;
            int n = n0 + half * 64 + c;
            float4 v = *reinterpret_cast<const float4*>(&smf[r * 68 + c]);
            v.x += badd[n + 0]; v.y += badd[n + 1];
            v.z += badd[n + 2]; v.w += badd[n + 3];
            *reinterpret_cast<float4*>(&g_xw[g][(size_t)(m0 + r) * 512 + n]) = v;
        }
        __syncthreads();
    }
}

// ===========================================================================
// Persistent recurrence kernel: 128 CTAs x 256 threads, single wave.
// Per step t:
//   Phase A: WMMA gemm hv[js][g] (CTA = (ntile8, gate4, js4)); in parallel,
//            cp.async-prefetch xw[t] row for batch b=ctaid into smem.
//   barrier
//   Phase B: CTA b does cos/cumprod-scan/gates for its batch row.
//   barrier
// ===========================================================================
__device__ __forceinline__ void gridbar(unsigned target) {
    __syncthreads();
    if (threadIdx.x == 0) {
        __threadfence();
        atomicAdd(&g_barrier, 1u);
        while (*((volatile unsigned*)&g_barrier) < target) { }
        __threadfence();
    }
    __syncthreads();
}

__device__ __forceinline__ float sigmoidf_(float x) {
    return 1.0f / (1.0f + expf(-x));
}

__global__ __launch_bounds__(256) void recurrence_persistent(float* __restrict__ out) {
    __shared__ __align__(16) __nv_bfloat16 sm[2 * 128 * SSTR + 2 * 64 * SSTR]; // 30KB
    __shared__ __align__(16) float sxw[4 * 512];                                // 8KB
    __shared__ float swt[8][4];
    __nv_bfloat16* sAh = sm;
    __nv_bfloat16* sAl = sm + 128 * SSTR;
    __nv_bfloat16* sBh = sm + 2 * 128 * SSTR;
    __nv_bfloat16* sBl = sm + 2 * 128 * SSTR + 64 * SSTR;

    const int tid = threadIdx.x, wid = tid >> 5, lane = tid & 31;
    const int cta = blockIdx.x;              // 0..127
    // GEMM mapping
    const int n0 = (cta & 7) * 64;
    const int g  = (cta >> 3) & 3;
    const int js = cta >> 5;
    const int kbase = js * 128;
    const int wm = wid >> 1;
    const int wn = wid & 1;
    // Scan mapping
    const int b = cta;

    const uint32_t sxw_base = (uint32_t)__cvta_generic_to_shared(sxw);

    for (int t = 0; t < T_STEPS; t++) {
        // ---- prefetch xw[t] for batch b (4 gates x 512 floats) via cp.async
#pragma unroll
        for (int it = 0; it < 2; it++) {
            int i = tid * 2 + it;            // 0..511 float4 index
            int pg = i >> 7, pk = (i & 127) * 4;
            const float* src = &g_xw[pg][((size_t)t * BSZ + b) * 512 + pk];
            asm volatile("cp.async.cg.shared.global [%0], [%1], 16;"
                         :: "r"(sxw_base + (uint32_t)i * 16), "l"(src) : "memory");
        }
        asm volatile("cp.async.commit_group;" ::: "memory");

        // ---- Phase A: hv[js][g][0:128][n0:n0+64] over K chunk [kbase, kbase+128)
        wmma::fragment<wmma::accumulator, 16, 16, 16, float> acc[2][2];
#pragma unroll
        for (int i = 0; i < 2; i++)
#pragma unroll
            for (int j = 0; j < 2; j++) wmma::fill_fragment(acc[i][j], 0.0f);

        for (int k0 = 0; k0 < 128; k0 += 32) {
#pragma unroll
            for (int it = 0; it < 2; it++) {
                int i = tid + it * 256;
                int r = i >> 2, c = (i & 3) * 8;
                size_t sA = (size_t)r * 512 + kbase + k0 + c;
                int d = r * SSTR + c;
                *reinterpret_cast<uint4*>(&sAh[d]) = *reinterpret_cast<const uint4*>(&g_h_h[sA]);
                *reinterpret_cast<uint4*>(&sAl[d]) = *reinterpret_cast<const uint4*>(&g_h_l[sA]);
            }
            {
                int r = tid >> 2, c = (tid & 3) * 8;
                if (r < 64) {
                    size_t sB = (size_t)(n0 + r) * 512 + kbase + k0 + c;
                    int d = r * SSTR + c;
                    *reinterpret_cast<uint4*>(&sBh[d]) = *reinterpret_cast<const uint4*>(&g_Whh[g][sB]);
                    *reinterpret_cast<uint4*>(&sBl[d]) = *reinterpret_cast<const uint4*>(&g_Whl[g][sB]);
                }
            }
            __syncthreads();

#pragma unroll
            for (int kk = 0; kk < 32; kk += 16) {
                wmma::fragment<wmma::matrix_a, 16, 16, 16, __nv_bfloat16, wmma::row_major> ah[2], al[2];
                wmma::fragment<wmma::matrix_b, 16, 16, 16, __nv_bfloat16, wmma::col_major> bh[2], bl[2];
#pragma unroll
                for (int i = 0; i < 2; i++) {
                    int row = wm * 32 + i * 16;
                    wmma::load_matrix_sync(ah[i], &sAh[row * SSTR + kk], SSTR);
                    wmma::load_matrix_sync(al[i], &sAl[row * SSTR + kk], SSTR);
                }
#pragma unroll
                for (int j = 0; j < 2; j++) {
                    int row = wn * 32 + j * 16;
                    wmma::load_matrix_sync(bh[j], &sBh[row * SSTR + kk], SSTR);
                    wmma::load_matrix_sync(bl[j], &sBl[row * SSTR + kk], SSTR);
                }
#pragma unroll
                for (int i = 0; i < 2; i++)
#pragma unroll
                    for (int j = 0; j < 2; j++) {
                        wmma::mma_sync(acc[i][j], ah[i], bh[j], acc[i][j]);
                        wmma::mma_sync(acc[i][j], ah[i], bl[j], acc[i][j]);
                        wmma::mma_sync(acc[i][j], al[i], bh[j], acc[i][j]);
                    }
            }
            __syncthreads();
        }

        float* dst = g_hv[js][g];
#pragma unroll
        for (int i = 0; i < 2; i++)
#pragma unroll
            for (int j = 0; j < 2; j++) {
                int m = wm * 32 + i * 16;
                int n = n0 + wn * 32 + j * 16;
                wmma::store_matrix_sync(&dst[(size_t)m * 512 + n], acc[i][j], 512,
                                        wmma::mem_row_major);
            }

        // finish prefetch before the barrier's trailing syncthreads
        asm volatile("cp.async.wait_group 0;" ::: "memory");
        gridbar(128u * (2u * t + 1u));

        // ---- Phase B: scan for batch row b; 256 threads x 2 consecutive elems
        {
            const int k = tid * 2;
            const int idx = b * 512 + k;
            float c0[4], c1[4], p[4];
#pragma unroll
            for (int q = 0; q < 4; q++) {
                float v0 = sxw[q * 512 + k];
                float v1 = sxw[q * 512 + k + 1];
#pragma unroll
                for (int s = 0; s < 4; s++) {
                    float2 hv = *reinterpret_cast<const float2*>(&g_hv[s][q][idx]);
                    v0 += hv.x; v1 += hv.y;
                }
                c0[q] = cosf(v0);
                c1[q] = cosf(v1);
                p[q]  = c0[q] * c1[q];
            }

            // inclusive warp scan of pair-products
            float inc[4];
#pragma unroll
            for (int q = 0; q < 4; q++) inc[q] = p[q];
#pragma unroll
            for (int o = 1; o < 32; o <<= 1) {
#pragma unroll
                for (int q = 0; q < 4; q++) {
                    float up = __shfl_up_sync(0xffffffffu, inc[q], o);
                    if (lane >= o) inc[q] *= up;
                }
            }
            // exclusive within warp
            float exc[4];
#pragma unroll
            for (int q = 0; q < 4; q++) {
                float up = __shfl_up_sync(0xffffffffu, inc[q], 1);
                exc[q] = (lane == 0) ? 1.0f : up;
            }
            if (lane == 31) {
#pragma unroll
                for (int q = 0; q < 4; q++) swt[wid][q] = inc[q];
            }
            __syncthreads();
            float pre[4] = {1.f, 1.f, 1.f, 1.f};
            for (int w = 0; w < wid; w++) {
#pragma unroll
                for (int q = 0; q < 4; q++) pre[q] *= swt[w][q];
            }

            float P0[4], P1[4];
#pragma unroll
            for (int q = 0; q < 4; q++) {
                float e = pre[q] * exc[q];
                P0[q] = e * c0[q];
                P1[q] = P0[q] * c1[q];
            }

            float2 cold = *reinterpret_cast<const float2*>(&g_c[idx]);

            float f0 = sigmoidf_(P0[0]), f1 = sigmoidf_(P1[0]);
            float i0 = sigmoidf_(P0[1]), i1 = sigmoidf_(P1[1]);
            float u0 = tanhf(P0[2]),     u1 = tanhf(P1[2]);
            float o0 = sigmoidf_(P0[3]), o1 = sigmoidf_(P1[3]);

            float cn0 = f0 * cold.x + i0 * u0;
            float cn1 = f1 * cold.y + i1 * u1;
            float h0 = o0 * tanhf(cn0);
            float h1 = o1 * tanhf(cn1);

            *reinterpret_cast<float2*>(&g_c[idx]) = make_float2(cn0, cn1);

            __nv_bfloat16 hh0, hl0, hh1, hl1;
            split_bf16(h0, hh0, hl0); split_bf16(h1, hh1, hl1);
            *reinterpret_cast<__nv_bfloat162*>(&g_h_h[idx]) = __nv_bfloat162(hh0, hh1);
            *reinterpret_cast<__nv_bfloat162*>(&g_h_l[idx]) = __nv_bfloat162(hl0, hl1);

            *reinterpret_cast<float2*>(&out[(size_t)t * STATE_N + idx]) = make_float2(h0, h1);
            if (t == T_STEPS - 1) {
                *reinterpret_cast<float2*>(&out[OUT_MAIN + idx]) = make_float2(h0, h1);
                *reinterpret_cast<float2*>(&out[OUT_MAIN + STATE_N + idx]) = make_float2(cn0, cn1);
            }
        }
        gridbar(128u * (2u * t + 2u));
    }
}

// ===========================================================================
__global__ void init_state() {
    int i = blockIdx.x * blockDim.x + threadIdx.x;
    if (i == 0) g_barrier = 0u;
    if (i < STATE_N) {
        g_c[i] = 0.f;
        g_h_h[i] = __float2bfloat16(0.f);
        g_h_l[i] = __float2bfloat16(0.f);
    }
}

extern "C" void kernel_launch(void* const* d_in, const int* in_sizes, int n_in,
                              void* d_out, int out_size) {
    const float* X = (const float*)d_in[0];
    GateParams gp;
    for (int g = 0; g < 4; g++) {
        gp.W[g]  = (const float*)d_in[1 + 3 * g];
        gp.b[g]  = (const float*)d_in[2 + 3 * g];
        gp.th[g] = (const float*)d_in[3 + 3 * g];
    }
    float* out = (float*)d_out;

    init_state<<<(STATE_N + 255) / 256, 256>>>();

    convert_x<<<(MTOT * 512 / 2) / 256, 256>>>(X);
    convert_w<<<(4 * 512 * 1024 / 2) / 256, 256>>>(gp);
    make_badd<<<8, 256>>>(gp);

    phase1_wmma<<<dim3(16, MTOT / 128), 256>>>();

    recurrence_persistent<<<128, 256>>>(out);
}

// round 5
// speedup vs baseline: 2.8176x; 1.6180x over previous
#include <cuda_runtime.h>
#include <cuda_fp16.h>
#include <mma.h>
#include <math.h>
#include <stdint.h>

using namespace nvcuda;

// Problem constants
#define T_STEPS 256
#define BSZ     128
#define HID     512
#define MTOT    (T_STEPS * BSZ)                  // 32768
#define OUT_MAIN ((size_t)T_STEPS * BSZ * HID)   // 16777216
#define STATE_N  (BSZ * HID)                     // 65536

// ---------------------------------------------------------------------------
// Device scratch
// ---------------------------------------------------------------------------
__device__ __align__(256) float g_xw[4][(size_t)MTOT * HID];   // 256 MiB
__device__ __align__(256) float g_u[4][STATE_N];               // cos values per step
__device__ __align__(256) float g_c[STATE_N];
__device__ __align__(256) __half g_hf[STATE_N];                // h state, fp16

__device__ __align__(256) __half g_Xf[(size_t)MTOT * 512];
__device__ __align__(256) __half g_Wxf[4][512 * 512];
__device__ __align__(256) __half g_Whf[4][512 * 512];
__device__ __align__(256) float g_badd[4][512];
__device__ unsigned g_barrier;

struct GateParams {
    const float* W[4];    // [512 x 1024]; cols [0,512)=Wx, [512,1024)=Wh
    const float* b[4];
    const float* th[4];
};

// ---------------------------------------------------------------------------
// Conversions: fp32 -> fp16
// ---------------------------------------------------------------------------
__global__ __launch_bounds__(256) void convert_x(const float* __restrict__ X) {
    size_t i = ((size_t)blockIdx.x * blockDim.x + threadIdx.x) * 2;
    float2 v = *reinterpret_cast<const float2*>(X + i);
    *reinterpret_cast<__half2*>(&g_Xf[i]) = __floats2half2_rn(v.x, v.y);
}

__global__ __launch_bounds__(256) void convert_w(GateParams gp) {
    size_t i = ((size_t)blockIdx.x * blockDim.x + threadIdx.x) * 2;
    int g = (int)(i >> 19);          // 512*1024 per gate
    size_t r = i & 524287;
    int n = (int)(r >> 10), k = (int)(r & 1023);
    float2 v = *reinterpret_cast<const float2*>(gp.W[g] + (size_t)n * 1024 + k);
    __half2 h = __floats2half2_rn(v.x, v.y);
    if (k < 512)
        *reinterpret_cast<__half2*>(&g_Wxf[g][(size_t)n * 512 + k]) = h;
    else
        *reinterpret_cast<__half2*>(&g_Whf[g][(size_t)n * 512 + (k - 512)]) = h;
}

__global__ void make_badd(GateParams gp) {
    int i = blockIdx.x * blockDim.x + threadIdx.x;
    int g = i >> 9, n = i & 511;
    g_badd[g][n] = gp.b[g][n] + gp.th[g][n];
}

// ===========================================================================
// Phase 1 via WMMA fp16 single-pass: xw[g][m][n] = X[m,:].Wx_g[n,:] + b + th
// CTA tile 128(m) x 128(n), K-chunks of 32; 8 warps = 4(m) x 2(n).
// ===========================================================================
#define SSTR1 40

__global__ __launch_bounds__(256) void phase1_wmma() {
    __shared__ __align__(16) char smraw[34816];    // max(staging 20KB, epi 34KB)
    __half* sA = reinterpret_cast<__half*>(smraw);
    __half* sB = sA + 128 * SSTR1;

    const int tid = threadIdx.x, wid = tid >> 5;
    const int nt = blockIdx.x;
    const int g  = nt >> 2;
    const int n0 = (nt & 3) * 128;
    const int m0 = blockIdx.y * 128;
    const int wm = wid >> 1;
    const int wn = wid & 1;

    wmma::fragment<wmma::accumulator, 16, 16, 16, float> acc[2][4];
#pragma unroll
    for (int i = 0; i < 2; i++)
#pragma unroll
        for (int j = 0; j < 4; j++) wmma::fill_fragment(acc[i][j], 0.0f);

    for (int k0 = 0; k0 < 512; k0 += 32) {
#pragma unroll
        for (int it = 0; it < 2; it++) {
            int i = tid + it * 256;        // 0..511
            int r = i >> 2, c = (i & 3) * 8;
            int d = r * SSTR1 + c;
            *reinterpret_cast<uint4*>(&sA[d]) =
                *reinterpret_cast<const uint4*>(&g_Xf[(size_t)(m0 + r) * 512 + k0 + c]);
            *reinterpret_cast<uint4*>(&sB[d]) =
                *reinterpret_cast<const uint4*>(&g_Wxf[g][(size_t)(n0 + r) * 512 + k0 + c]);
        }
        __syncthreads();

#pragma unroll
        for (int kk = 0; kk < 32; kk += 16) {
            wmma::fragment<wmma::matrix_a, 16, 16, 16, __half, wmma::row_major> a[2];
            wmma::fragment<wmma::matrix_b, 16, 16, 16, __half, wmma::col_major> bfr[4];
#pragma unroll
            for (int i = 0; i < 2; i++)
                wmma::load_matrix_sync(a[i], &sA[(wm * 32 + i * 16) * SSTR1 + kk], SSTR1);
#pragma unroll
            for (int j = 0; j < 4; j++)
                wmma::load_matrix_sync(bfr[j], &sB[(wn * 64 + j * 16) * SSTR1 + kk], SSTR1);
#pragma unroll
            for (int i = 0; i < 2; i++)
#pragma unroll
                for (int j = 0; j < 4; j++)
                    wmma::mma_sync(acc[i][j], a[i], bfr[j], acc[i][j]);
        }
        __syncthreads();
    }

    float* smf = reinterpret_cast<float*>(smraw);
    const float* __restrict__ badd = g_badd[g];
#pragma unroll
    for (int half = 0; half < 2; half++) {
        if (wn == half) {
#pragma unroll
            for (int i = 0; i < 2; i++)
#pragma unroll
                for (int j = 0; j < 4; j++)
                    wmma::store_matrix_sync(&smf[(wm * 32 + i * 16) * 68 + j * 16],
                                            acc[i][j], 68, wmma::mem_row_major);
        }
        __syncthreads();
#pragma unroll
        for (int it = 0; it < 8; it++) {
            int i = tid + it * 256;
            int r = i >> 4, c = (i & 15) * 4;
            int n = n0 + half * 64 + c;
            float4 v = *reinterpret_cast<const float4*>(&smf[r * 68 + c]);
            v.x += badd[n + 0]; v.y += badd[n + 1];
            v.z += badd[n + 2]; v.w += badd[n + 3];
            *reinterpret_cast<float4*>(&g_xw[g][(size_t)(m0 + r) * 512 + n]) = v;
        }
        __syncthreads();
    }
}

// ===========================================================================
// Persistent recurrence: 128 CTAs x 256 threads, single wave.
// Phase A: CTA = (m-half 2, n-tile 16 of width 32, gate 4); full K=512,
//   fp16 single-pass WMMA, double-buffered cp.async staging; epilogue
//   computes g_u = __cosf(xw + hv) with xw cp.async-prefetched.
// Phase B: CTA b scans its batch row over g_u, applies gates, updates state.
// ===========================================================================
#define ASTR 72                    // K-chunk 64 + 8 pad (halves)
#define BUF_HALVES ((64 + 32) * ASTR)          // 6912 halves = 13824 B

__device__ __forceinline__ void gridbar(unsigned target) {
    __syncthreads();
    if (threadIdx.x == 0) {
        __threadfence();
        atomicAdd(&g_barrier, 1u);
        while (*((volatile unsigned*)&g_barrier) < target) { }
        __threadfence();
    }
    __syncthreads();
}

__device__ __forceinline__ float sigmoidf_(float x) {
    return 1.0f / (1.0f + expf(-x));
}

__global__ __launch_bounds__(256) void recurrence_persistent(float* __restrict__ out) {
    __shared__ __align__(16) __half sbuf[2 * BUF_HALVES];   // 27648 B
    __shared__ __align__(16) float sxw[64 * 32];            // 8192 B
    __shared__ float swt[8][4];

    const int tid = threadIdx.x, wid = tid >> 5, lane = tid & 31;
    const int cta = blockIdx.x;              // 0..127
    // Phase A mapping
    const int mh = cta & 1;
    const int nt = (cta >> 1) & 15;
    const int g  = cta >> 5;
    const int n0 = nt * 32;
    const int b0 = mh * 64;
    const int wm = wid >> 1;                 // 0..3 (m 16-rows)
    const int wn = wid & 1;                  // 0..1 (n 16-cols)
    // Phase B mapping
    const int b = cta;

    const uint32_t sxw_addr = (uint32_t)__cvta_generic_to_shared(sxw);
    const uint32_t sbuf_addr = (uint32_t)__cvta_generic_to_shared(sbuf);

    for (int t = 0; t < T_STEPS; t++) {
        // ---- prefetch xw tile (64 rows x 32 cols fp32) + stage chunk 0 (group 0)
#pragma unroll
        for (int it = 0; it < 2; it++) {
            int i = tid + it * 256;          // 0..511
            int r = i >> 3, q = (i & 7) * 4;
            const float* src = &g_xw[g][((size_t)t * BSZ + b0 + r) * 512 + n0 + q];
            asm volatile("cp.async.cg.shared.global [%0], [%1], 16;"
                         :: "r"(sxw_addr + (uint32_t)(r * 32 + q) * 4), "l"(src) : "memory");
        }
        // stage function for K-chunk c into buffer c&1
        auto stage = [&](int c) {
            const int k0 = c * 64;
            const uint32_t base = sbuf_addr + (uint32_t)(c & 1) * (BUF_HALVES * 2);
            // A: 64 rows x 64 halves (8 x 16B per row) -> 512 16B ops
#pragma unroll
            for (int it = 0; it < 2; it++) {
                int i = tid + it * 256;
                int r = i >> 3, q = (i & 7) * 8;
                const __half* src = &g_hf[(size_t)(b0 + r) * 512 + k0 + q];
                asm volatile("cp.async.cg.shared.global [%0], [%1], 16;"
                             :: "r"(base + (uint32_t)(r * ASTR + q) * 2), "l"(src) : "memory");
            }
            // B: 32 rows x 64 halves -> 256 16B ops
            {
                int r = tid >> 3, q = (tid & 7) * 8;
                const __half* src = &g_Whf[g][(size_t)(n0 + r) * 512 + k0 + q];
                asm volatile("cp.async.cg.shared.global [%0], [%1], 16;"
                             :: "r"(base + (uint32_t)(64 * ASTR + r * ASTR + q) * 2), "l"(src) : "memory");
            }
            asm volatile("cp.async.commit_group;" ::: "memory");
        };

        stage(0);   // group also containing the xw prefetch

        wmma::fragment<wmma::accumulator, 16, 16, 16, float> acc;
        wmma::fill_fragment(acc, 0.0f);

        for (int c = 0; c < 8; c++) {
            if (c < 7) {
                stage(c + 1);
                asm volatile("cp.async.wait_group 1;" ::: "memory");
            } else {
                asm volatile("cp.async.wait_group 0;" ::: "memory");
            }
            __syncthreads();
            const __half* sA = sbuf + (c & 1) * BUF_HALVES;
            const __half* sB = sA + 64 * ASTR;
#pragma unroll
            for (int kk = 0; kk < 64; kk += 16) {
                wmma::fragment<wmma::matrix_a, 16, 16, 16, __half, wmma::row_major> a;
                wmma::fragment<wmma::matrix_b, 16, 16, 16, __half, wmma::col_major> bb;
                wmma::load_matrix_sync(a,  &sA[(wm * 16) * ASTR + kk], ASTR);
                wmma::load_matrix_sync(bb, &sB[(wn * 16) * ASTR + kk], ASTR);
                wmma::mma_sync(acc, a, bb, acc);
            }
            __syncthreads();
        }

        // ---- epilogue: u = cos(xw + hv), through smem (overlay on sbuf)
        {
            float* smf = reinterpret_cast<float*>(sbuf);   // 64 x 36 floats
            wmma::store_matrix_sync(&smf[(wm * 16) * 36 + wn * 16], acc, 36,
                                    wmma::mem_row_major);
            __syncthreads();
#pragma unroll
            for (int it = 0; it < 8; it++) {
                int i = tid + it * 256;           // 0..2047
                int r = i >> 5, c = i & 31;
                float v = smf[r * 36 + c] + sxw[r * 32 + c];
                g_u[g][(size_t)(b0 + r) * 512 + n0 + c] = __cosf(v);
            }
        }
        gridbar(128u * (2u * t + 1u));

        // ---- Phase B: scan + gates for batch row b
        {
            const int k = tid * 2;
            const int idx = b * 512 + k;
            float c0[4], c1[4], inc[4];
#pragma unroll
            for (int q = 0; q < 4; q++) {
                float2 uv = *reinterpret_cast<const float2*>(&g_u[q][idx]);
                c0[q] = uv.x; c1[q] = uv.y;
                inc[q] = c0[q] * c1[q];
            }

#pragma unroll
            for (int o = 1; o < 32; o <<= 1) {
#pragma unroll
                for (int q = 0; q < 4; q++) {
                    float up = __shfl_up_sync(0xffffffffu, inc[q], o);
                    if (lane >= o) inc[q] *= up;
                }
            }
            float exc[4];
#pragma unroll
            for (int q = 0; q < 4; q++) {
                float up = __shfl_up_sync(0xffffffffu, inc[q], 1);
                exc[q] = (lane == 0) ? 1.0f : up;
            }
            if (lane == 31) {
#pragma unroll
                for (int q = 0; q < 4; q++) swt[wid][q] = inc[q];
            }
            __syncthreads();
            float pre[4] = {1.f, 1.f, 1.f, 1.f};
            for (int w = 0; w < wid; w++) {
#pragma unroll
                for (int q = 0; q < 4; q++) pre[q] *= swt[w][q];
            }

            float P0[4], P1[4];
#pragma unroll
            for (int q = 0; q < 4; q++) {
                float e = pre[q] * exc[q];
                P0[q] = e * c0[q];
                P1[q] = P0[q] * c1[q];
            }

            float2 cold = *reinterpret_cast<const float2*>(&g_c[idx]);

            float f0 = sigmoidf_(P0[0]), f1 = sigmoidf_(P1[0]);
            float i0 = sigmoidf_(P0[1]), i1 = sigmoidf_(P1[1]);
            float u0 = tanhf(P0[2]),     u1 = tanhf(P1[2]);
            float o0 = sigmoidf_(P0[3]), o1 = sigmoidf_(P1[3]);

            float cn0 = f0 * cold.x + i0 * u0;
            float cn1 = f1 * cold.y + i1 * u1;
            float h0 = o0 * tanhf(cn0);
            float h1 = o1 * tanhf(cn1);

            *reinterpret_cast<float2*>(&g_c[idx]) = make_float2(cn0, cn1);
            *reinterpret_cast<__half2*>(&g_hf[idx]) = __floats2half2_rn(h0, h1);

            *reinterpret_cast<float2*>(&out[(size_t)t * STATE_N + idx]) = make_float2(h0, h1);
            if (t == T_STEPS - 1) {
                *reinterpret_cast<float2*>(&out[OUT_MAIN + idx]) = make_float2(h0, h1);
                *reinterpret_cast<float2*>(&out[OUT_MAIN + STATE_N + idx]) = make_float2(cn0, cn1);
            }
        }
        gridbar(128u * (2u * t + 2u));
    }
}

// ===========================================================================
__global__ void init_state() {
    int i = blockIdx.x * blockDim.x + threadIdx.x;
    if (i == 0) g_barrier = 0u;
    if (i < STATE_N) {
        g_c[i] = 0.f;
        g_hf[i] = __float2half(0.f);
    }
}

extern "C" void kernel_launch(void* const* d_in, const int* in_sizes, int n_in,
                              void* d_out, int out_size) {
    const float* X = (const float*)d_in[0];
    GateParams gp;
    for (int g = 0; g < 4; g++) {
        gp.W[g]  = (const float*)d_in[1 + 3 * g];
        gp.b[g]  = (const float*)d_in[2 + 3 * g];
        gp.th[g] = (const float*)d_in[3 + 3 * g];
    }
    float* out = (float*)d_out;

    init_state<<<(STATE_N + 255) / 256, 256>>>();

    convert_x<<<(MTOT * 512 / 2) / 256, 256>>>(X);
    convert_w<<<(4 * 512 * 1024 / 2) / 256, 256>>>(gp);
    make_badd<<<8, 256>>>(gp);

    phase1_wmma<<<dim3(16, MTOT / 128), 256>>>();

    recurrence_persistent<<<128, 256>>>(out);
}

// round 6
// speedup vs baseline: 3.4800x; 1.2351x over previous
#include <cuda_runtime.h>
#include <cuda_fp16.h>
#include <mma.h>
#include <math.h>
#include <stdint.h>

using namespace nvcuda;

// Problem constants
#define T_STEPS 256
#define BSZ     128
#define HID     512
#define MTOT    (T_STEPS * BSZ)                  // 32768
#define OUT_MAIN ((size_t)T_STEPS * BSZ * HID)   // 16777216
#define STATE_N  (BSZ * HID)                     // 65536

// ---------------------------------------------------------------------------
// Device scratch
// ---------------------------------------------------------------------------
__device__ __align__(256) float g_xw[4][(size_t)MTOT * HID];   // 256 MiB
__device__ __align__(256) float g_u[4][STATE_N];               // cos values per step
__device__ __align__(256) float g_c[STATE_N];
__device__ __align__(256) __half g_hf[STATE_N];                // h state, fp16

__device__ __align__(256) __half g_Xf[(size_t)MTOT * 512];
__device__ __align__(256) __half g_Wxf[4][512 * 512];
__device__ __align__(256) __half g_Whf[4][512 * 512];
__device__ __align__(256) float g_badd[4][512];
__device__ unsigned g_barrier;

struct GateParams {
    const float* W[4];
    const float* b[4];
    const float* th[4];
};

// ---------------------------------------------------------------------------
// Conversions
// ---------------------------------------------------------------------------
__global__ __launch_bounds__(256) void convert_x(const float* __restrict__ X) {
    size_t i = ((size_t)blockIdx.x * blockDim.x + threadIdx.x) * 2;
    float2 v = *reinterpret_cast<const float2*>(X + i);
    *reinterpret_cast<__half2*>(&g_Xf[i]) = __floats2half2_rn(v.x, v.y);
}

__global__ __launch_bounds__(256) void convert_w(GateParams gp) {
    size_t i = ((size_t)blockIdx.x * blockDim.x + threadIdx.x) * 2;
    int g = (int)(i >> 19);
    size_t r = i & 524287;
    int n = (int)(r >> 10), k = (int)(r & 1023);
    float2 v = *reinterpret_cast<const float2*>(gp.W[g] + (size_t)n * 1024 + k);
    __half2 h = __floats2half2_rn(v.x, v.y);
    if (k < 512)
        *reinterpret_cast<__half2*>(&g_Wxf[g][(size_t)n * 512 + k]) = h;
    else
        *reinterpret_cast<__half2*>(&g_Whf[g][(size_t)n * 512 + (k - 512)]) = h;
}

__global__ void make_badd(GateParams gp) {
    int i = blockIdx.x * blockDim.x + threadIdx.x;
    int g = i >> 9, n = i & 511;
    g_badd[g][n] = gp.b[g][n] + gp.th[g][n];
}

// ===========================================================================
// Phase 1: fp16 WMMA, cp.async double-buffered, K-chunks of 32.
// CTA 128(m) x 128(n); 8 warps = 4(m) x 2(n).
// smem: 2 bufs x (A 128x40 + B 128x40) halves = 40960 B (epi overlay fits).
// ===========================================================================
#define SSTR1 40

__global__ __launch_bounds__(256) void phase1_wmma() {
    __shared__ __align__(16) char smraw[40960];

    const int tid = threadIdx.x, wid = tid >> 5;
    const int nt = blockIdx.x;
    const int g  = nt >> 2;
    const int n0 = (nt & 3) * 128;
    const int m0 = blockIdx.y * 128;
    const int wm = wid >> 1;
    const int wn = wid & 1;

    const uint32_t smaddr = (uint32_t)__cvta_generic_to_shared(smraw);

    auto stage = [&](int c) {
        const int k0 = c * 32;
        const uint32_t base = smaddr + (uint32_t)(c & 1) * 20480;
#pragma unroll
        for (int it = 0; it < 4; it++) {
            int i = tid + it * 256;              // 0..1023
            int mat = i >> 9;                    // 0 = A(X), 1 = B(W)
            int r = (i >> 2) & 127, s = i & 3;   // 4 x 16B segs per row
            const __half* src = mat
                ? &g_Wxf[g][(size_t)(n0 + r) * 512 + k0 + s * 8]
                : &g_Xf[(size_t)(m0 + r) * 512 + k0 + s * 8];
            asm volatile("cp.async.cg.shared.global [%0], [%1], 16;"
                :: "r"(base + (uint32_t)mat * 10240 + (uint32_t)(r * SSTR1 + s * 8) * 2),
                   "l"(src) : "memory");
        }
        asm volatile("cp.async.commit_group;" ::: "memory");
    };

    wmma::fragment<wmma::accumulator, 16, 16, 16, float> acc[2][4];
#pragma unroll
    for (int i = 0; i < 2; i++)
#pragma unroll
        for (int j = 0; j < 4; j++) wmma::fill_fragment(acc[i][j], 0.0f);

    stage(0);
    for (int c = 0; c < 16; c++) {
        if (c < 15) {
            stage(c + 1);
            asm volatile("cp.async.wait_group 1;" ::: "memory");
        } else {
            asm volatile("cp.async.wait_group 0;" ::: "memory");
        }
        __syncthreads();
        const __half* sA = reinterpret_cast<const __half*>(smraw + (c & 1) * 20480);
        const __half* sB = sA + 128 * SSTR1;
#pragma unroll
        for (int kk = 0; kk < 32; kk += 16) {
            wmma::fragment<wmma::matrix_a, 16, 16, 16, __half, wmma::row_major> a[2];
            wmma::fragment<wmma::matrix_b, 16, 16, 16, __half, wmma::col_major> bfr[4];
#pragma unroll
            for (int i = 0; i < 2; i++)
                wmma::load_matrix_sync(a[i], &sA[(wm * 32 + i * 16) * SSTR1 + kk], SSTR1);
#pragma unroll
            for (int j = 0; j < 4; j++)
                wmma::load_matrix_sync(bfr[j], &sB[(wn * 64 + j * 16) * SSTR1 + kk], SSTR1);
#pragma unroll
            for (int i = 0; i < 2; i++)
#pragma unroll
                for (int j = 0; j < 4; j++)
                    wmma::mma_sync(acc[i][j], a[i], bfr[j], acc[i][j]);
        }
        __syncthreads();
    }

    float* smf = reinterpret_cast<float*>(smraw);
    const float* __restrict__ badd = g_badd[g];
#pragma unroll
    for (int half = 0; half < 2; half++) {
        if (wn == half) {
#pragma unroll
            for (int i = 0; i < 2; i++)
#pragma unroll
                for (int j = 0; j < 4; j++)
                    wmma::store_matrix_sync(&smf[(wm * 32 + i * 16) * 68 + j * 16],
                                            acc[i][j], 68, wmma::mem_row_major);
        }
        __syncthreads();
#pragma unroll
        for (int it = 0; it < 8; it++) {
            int i = tid + it * 256;
            int r = i >> 4, c = (i & 15) * 4;
            int n = n0 + half * 64 + c;
            float4 v = *reinterpret_cast<const float4*>(&smf[r * 68 + c]);
            v.x += badd[n + 0]; v.y += badd[n + 1];
            v.z += badd[n + 2]; v.w += badd[n + 3];
            *reinterpret_cast<float4*>(&g_xw[g][(size_t)(m0 + r) * 512 + n]) = v;
        }
        __syncthreads();
    }
}

// ===========================================================================
// Persistent recurrence: 128 CTAs x 256 threads.
// Phase A: CTA = (m-quarter 4, n-tile 8 of width 64, gate 4); Wh fragments
//   persistent in REGISTERS (32 b-frags/warp), h staged via one cp.async
//   group per step, xw prefetched during previous phase B.
//   Epilogue: g_u = __cosf(xw + hv).
// Phase B: CTA b scans batch row b, gates, state update.
// ===========================================================================
#define HSTR 520     // 512 + 8 pad, halves

__device__ __forceinline__ void gridbar(unsigned target) {
    __syncthreads();
    if (threadIdx.x == 0) {
        __threadfence();
        atomicAdd(&g_barrier, 1u);
        while (*((volatile unsigned*)&g_barrier) < target) { }
        __threadfence();
    }
    __syncthreads();
}

__device__ __forceinline__ float sigmoidf_(float x) {
    return 1.0f / (1.0f + expf(-x));
}

__global__ __launch_bounds__(256, 1) void recurrence_persistent(float* __restrict__ out) {
    __shared__ __align__(16) __half sH[32 * HSTR];     // 33280 B (epi float overlay)
    __shared__ __align__(16) float sxw[32 * 64];       // 8192 B
    __shared__ float swt[8][4];

    const int tid = threadIdx.x, wid = tid >> 5, lane = tid & 31;
    const int cta = blockIdx.x;              // 0..127
    // Phase A mapping
    const int mq = cta & 3;                  // batch quarter
    const int nt = (cta >> 2) & 7;
    const int g  = cta >> 5;
    const int n0 = nt * 64;
    const int b0 = mq * 32;
    const int wm = wid & 1;                  // m 16-row block (0..1)
    const int wn = wid >> 1;                 // n 16-col block (0..3)
    // Phase B mapping
    const int b = cta;

    const uint32_t sH_addr  = (uint32_t)__cvta_generic_to_shared(sH);
    const uint32_t sxw_addr = (uint32_t)__cvta_generic_to_shared(sxw);

    // ---- Preload Wh fragments into registers (2 halves through sH) ----
    wmma::fragment<wmma::matrix_b, 16, 16, 16, __half, wmma::col_major> bfr[32];
#pragma unroll
    for (int half = 0; half < 2; half++) {
        __syncthreads();
#pragma unroll
        for (int it = 0; it < 8; it++) {
            int i = tid + it * 256;          // 0..2047: 32 rows x 64 segs
            int r = i >> 6, s = i & 63;
            *reinterpret_cast<uint4*>(reinterpret_cast<char*>(sH) + (r * HSTR + s * 8) * 2) =
                *reinterpret_cast<const uint4*>(&g_Whf[g][(size_t)(n0 + half * 32 + r) * 512 + s * 8]);
        }
        __syncthreads();
        if ((wn >> 1) == half) {
            const int rloc = (wn & 1) * 16;
#pragma unroll
            for (int kk = 0; kk < 32; kk++)
                wmma::load_matrix_sync(bfr[kk], &sH[rloc * HSTR + kk * 16], HSTR);
        }
    }
    __syncthreads();

    // stage xw(t) into sxw: 32 rows x 64 floats = 512 x 16B segs
    auto stage_xw = [&](int t) {
#pragma unroll
        for (int it = 0; it < 2; it++) {
            int i = tid + it * 256;          // 0..511
            int r = i >> 4, s = i & 15;
            const float* src = &g_xw[g][((size_t)t * BSZ + b0 + r) * 512 + n0 + s * 4];
            asm volatile("cp.async.cg.shared.global [%0], [%1], 16;"
                :: "r"(sxw_addr + (uint32_t)(r * 64 + s * 4) * 4), "l"(src) : "memory");
        }
        asm volatile("cp.async.commit_group;" ::: "memory");
    };

    stage_xw(0);

    for (int t = 0; t < T_STEPS; t++) {
        // ---- stage h tile: 32 rows x 512 halves = 2048 x 16B segs
#pragma unroll
        for (int it = 0; it < 8; it++) {
            int i = tid + it * 256;
            int r = i >> 6, s = i & 63;
            const __half* src = &g_hf[(size_t)(b0 + r) * 512 + s * 8];
            asm volatile("cp.async.cg.shared.global [%0], [%1], 16;"
                :: "r"(sH_addr + (uint32_t)(r * HSTR + s * 8) * 2), "l"(src) : "memory");
        }
        asm volatile("cp.async.commit_group;" ::: "memory");
        asm volatile("cp.async.wait_group 0;" ::: "memory");
        __syncthreads();

        // ---- MMA: acc(16m x 16n) over K=512
        wmma::fragment<wmma::accumulator, 16, 16, 16, float> acc;
        wmma::fill_fragment(acc, 0.0f);
#pragma unroll
        for (int kk = 0; kk < 32; kk++) {
            wmma::fragment<wmma::matrix_a, 16, 16, 16, __half, wmma::row_major> a;
            wmma::load_matrix_sync(a, &sH[(wm * 16) * HSTR + kk * 16], HSTR);
            wmma::mma_sync(acc, a, bfr[kk], acc);
        }
        __syncthreads();   // all warps done reading sH before overlay write

        // ---- epilogue: u = cos(xw + hv)
        {
            float* smf = reinterpret_cast<float*>(sH);   // 32 x 68 overlay
            wmma::store_matrix_sync(&smf[(wm * 16) * 68 + wn * 16], acc, 68,
                                    wmma::mem_row_major);
            __syncthreads();
#pragma unroll
            for (int it = 0; it < 8; it++) {
                int i = tid + it * 256;       // 0..2047
                int r = i >> 6, c = i & 63;
                float v = smf[r * 68 + c] + sxw[r * 64 + c];
                g_u[g][(size_t)(b0 + r) * 512 + n0 + c] = __cosf(v);
            }
        }
        gridbar(128u * (2u * t + 1u));

        // ---- Phase B: prefetch next xw, then scan + gates for batch row b
        if (t + 1 < T_STEPS) stage_xw(t + 1);
        {
            const int k = tid * 2;
            const int idx = b * 512 + k;
            float c0[4], c1[4], inc[4];
#pragma unroll
            for (int q = 0; q < 4; q++) {
                float2 uv = *reinterpret_cast<const float2*>(&g_u[q][idx]);
                c0[q] = uv.x; c1[q] = uv.y;
                inc[q] = c0[q] * c1[q];
            }

#pragma unroll
            for (int o = 1; o < 32; o <<= 1) {
#pragma unroll
                for (int q = 0; q < 4; q++) {
                    float up = __shfl_up_sync(0xffffffffu, inc[q], o);
                    if (lane >= o) inc[q] *= up;
                }
            }
            float exc[4];
#pragma unroll
            for (int q = 0; q < 4; q++) {
                float up = __shfl_up_sync(0xffffffffu, inc[q], 1);
                exc[q] = (lane == 0) ? 1.0f : up;
            }
            if (lane == 31) {
#pragma unroll
                for (int q = 0; q < 4; q++) swt[wid][q] = inc[q];
            }
            __syncthreads();
            float pre[4] = {1.f, 1.f, 1.f, 1.f};
            for (int w = 0; w < wid; w++) {
#pragma unroll
                for (int q = 0; q < 4; q++) pre[q] *= swt[w][q];
            }

            float P0[4], P1[4];
#pragma unroll
            for (int q = 0; q < 4; q++) {
                float e = pre[q] * exc[q];
                P0[q] = e * c0[q];
                P1[q] = P0[q] * c1[q];
            }

            float2 cold = *reinterpret_cast<const float2*>(&g_c[idx]);

            float f0 = sigmoidf_(P0[0]), f1 = sigmoidf_(P1[0]);
            float i0 = sigmoidf_(P0[1]), i1 = sigmoidf_(P1[1]);
            float u0 = tanhf(P0[2]),     u1 = tanhf(P1[2]);
            float o0 = sigmoidf_(P0[3]), o1 = sigmoidf_(P1[3]);

            float cn0 = f0 * cold.x + i0 * u0;
            float cn1 = f1 * cold.y + i1 * u1;
            float h0 = o0 * tanhf(cn0);
            float h1 = o1 * tanhf(cn1);

            *reinterpret_cast<float2*>(&g_c[idx]) = make_float2(cn0, cn1);
            *reinterpret_cast<__half2*>(&g_hf[idx]) = __floats2half2_rn(h0, h1);

            *reinterpret_cast<float2*>(&out[(size_t)t * STATE_N + idx]) = make_float2(h0, h1);
            if (t == T_STEPS - 1) {
                *reinterpret_cast<float2*>(&out[OUT_MAIN + idx]) = make_float2(h0, h1);
                *reinterpret_cast<float2*>(&out[OUT_MAIN + STATE_N + idx]) = make_float2(cn0, cn1);
            }
        }
        gridbar(128u * (2u * t + 2u));
    }
}

// ===========================================================================
__global__ void init_state() {
    int i = blockIdx.x * blockDim.x + threadIdx.x;
    if (i == 0) g_barrier = 0u;
    if (i < STATE_N) {
        g_c[i] = 0.f;
        g_hf[i] = __float2half(0.f);
    }
}

extern "C" void kernel_launch(void* const* d_in, const int* in_sizes, int n_in,
                              void* d_out, int out_size) {
    const float* X = (const float*)d_in[0];
    GateParams gp;
    for (int g = 0; g < 4; g++) {
        gp.W[g]  = (const float*)d_in[1 + 3 * g];
        gp.b[g]  = (const float*)d_in[2 + 3 * g];
        gp.th[g] = (const float*)d_in[3 + 3 * g];
    }
    float* out = (float*)d_out;

    init_state<<<(STATE_N + 255) / 256, 256>>>();

    convert_x<<<(MTOT * 512 / 2) / 256, 256>>>(X);
    convert_w<<<(4 * 512 * 1024 / 2) / 256, 256>>>(gp);
    make_badd<<<8, 256>>>(gp);

    phase1_wmma<<<dim3(16, MTOT / 128), 256>>>();

    recurrence_persistent<<<128, 256>>>(out);
}

// round 7
// speedup vs baseline: 3.6359x; 1.0448x over previous
#include <cuda_runtime.h>
#include <cuda_fp16.h>
#include <mma.h>
#include <math.h>
#include <stdint.h>

using namespace nvcuda;

// Problem constants
#define T_STEPS 256
#define BSZ     128
#define HID     512
#define MTOT    (T_STEPS * BSZ)                  // 32768
#define OUT_MAIN ((size_t)T_STEPS * BSZ * HID)   // 16777216
#define STATE_N  (BSZ * HID)                     // 65536

// ---------------------------------------------------------------------------
// Device scratch
// ---------------------------------------------------------------------------
__device__ __align__(256) __half g_xwh[4][(size_t)MTOT * 512];  // 128 MiB (fp16)
__device__ __align__(256) float g_u[4][STATE_N];                // cos values per step
__device__ __align__(256) float g_c[STATE_N];
__device__ __align__(256) __half g_hf[STATE_N];                 // h state, fp16

__device__ __align__(256) __half g_Xf[(size_t)MTOT * 512];
__device__ __align__(256) __half g_Wxf[4][512 * 512];
__device__ __align__(256) __half g_Whf[4][512 * 512];
__device__ unsigned g_barrier;

struct GateParams {
    const float* W[4];
    const float* b[4];
    const float* th[4];
};

// ---------------------------------------------------------------------------
// Conversions
// ---------------------------------------------------------------------------
__global__ __launch_bounds__(256) void convert_x(const float* __restrict__ X) {
    size_t i = ((size_t)blockIdx.x * blockDim.x + threadIdx.x) * 2;
    float2 v = *reinterpret_cast<const float2*>(X + i);
    *reinterpret_cast<__half2*>(&g_Xf[i]) = __floats2half2_rn(v.x, v.y);
}

__global__ __launch_bounds__(256) void convert_w(GateParams gp) {
    size_t i = ((size_t)blockIdx.x * blockDim.x + threadIdx.x) * 2;
    int g = (int)(i >> 19);
    size_t r = i & 524287;
    int n = (int)(r >> 10), k = (int)(r & 1023);
    float2 v = *reinterpret_cast<const float2*>(gp.W[g] + (size_t)n * 1024 + k);
    __half2 h = __floats2half2_rn(v.x, v.y);
    if (k < 512)
        *reinterpret_cast<__half2*>(&g_Wxf[g][(size_t)n * 512 + k]) = h;
    else
        *reinterpret_cast<__half2*>(&g_Whf[g][(size_t)n * 512 + (k - 512)]) = h;
}

// ===========================================================================
// Phase 1: fp16 WMMA, cp.async double-buffered; writes g_xwh (fp16) with
// bias+theta folded in.  CTA 128(m) x 128(n); 8 warps = 4(m) x 2(n).
// ===========================================================================
#define SSTR1 40

__global__ __launch_bounds__(256) void phase1_wmma(GateParams gp) {
    __shared__ __align__(16) char smraw[40960];

    const int tid = threadIdx.x, wid = tid >> 5;
    const int nt = blockIdx.x;
    const int g  = nt >> 2;
    const int n0 = (nt & 3) * 128;
    const int m0 = blockIdx.y * 128;
    const int wm = wid >> 1;
    const int wn = wid & 1;

    const uint32_t smaddr = (uint32_t)__cvta_generic_to_shared(smraw);

    auto stage = [&](int c) {
        const int k0 = c * 32;
        const uint32_t base = smaddr + (uint32_t)(c & 1) * 20480;
#pragma unroll
        for (int it = 0; it < 4; it++) {
            int i = tid + it * 256;
            int mat = i >> 9;
            int r = (i >> 2) & 127, s = i & 3;
            const __half* src = mat
                ? &g_Wxf[g][(size_t)(n0 + r) * 512 + k0 + s * 8]
                : &g_Xf[(size_t)(m0 + r) * 512 + k0 + s * 8];
            asm volatile("cp.async.cg.shared.global [%0], [%1], 16;"
                :: "r"(base + (uint32_t)mat * 10240 + (uint32_t)(r * SSTR1 + s * 8) * 2),
                   "l"(src) : "memory");
        }
        asm volatile("cp.async.commit_group;" ::: "memory");
    };

    wmma::fragment<wmma::accumulator, 16, 16, 16, float> acc[2][4];
#pragma unroll
    for (int i = 0; i < 2; i++)
#pragma unroll
        for (int j = 0; j < 4; j++) wmma::fill_fragment(acc[i][j], 0.0f);

    stage(0);
    for (int c = 0; c < 16; c++) {
        if (c < 15) {
            stage(c + 1);
            asm volatile("cp.async.wait_group 1;" ::: "memory");
        } else {
            asm volatile("cp.async.wait_group 0;" ::: "memory");
        }
        __syncthreads();
        const __half* sA = reinterpret_cast<const __half*>(smraw + (c & 1) * 20480);
        const __half* sB = sA + 128 * SSTR1;
#pragma unroll
        for (int kk = 0; kk < 32; kk += 16) {
            wmma::fragment<wmma::matrix_a, 16, 16, 16, __half, wmma::row_major> a[2];
            wmma::fragment<wmma::matrix_b, 16, 16, 16, __half, wmma::col_major> bfr[4];
#pragma unroll
            for (int i = 0; i < 2; i++)
                wmma::load_matrix_sync(a[i], &sA[(wm * 32 + i * 16) * SSTR1 + kk], SSTR1);
#pragma unroll
            for (int j = 0; j < 4; j++)
                wmma::load_matrix_sync(bfr[j], &sB[(wn * 64 + j * 16) * SSTR1 + kk], SSTR1);
#pragma unroll
            for (int i = 0; i < 2; i++)
#pragma unroll
                for (int j = 0; j < 4; j++)
                    wmma::mma_sync(acc[i][j], a[i], bfr[j], acc[i][j]);
        }
        __syncthreads();
    }

    float* smf = reinterpret_cast<float*>(smraw);
    const float* __restrict__ bb = gp.b[g];
    const float* __restrict__ tt = gp.th[g];
#pragma unroll
    for (int half = 0; half < 2; half++) {
        if (wn == half) {
#pragma unroll
            for (int i = 0; i < 2; i++)
#pragma unroll
                for (int j = 0; j < 4; j++)
                    wmma::store_matrix_sync(&smf[(wm * 32 + i * 16) * 68 + j * 16],
                                            acc[i][j], 68, wmma::mem_row_major);
        }
        __syncthreads();
#pragma unroll
        for (int it = 0; it < 8; it++) {
            int i = tid + it * 256;
            int r = i >> 4, c = (i & 15) * 4;
            int n = n0 + half * 64 + c;
            float4 v = *reinterpret_cast<const float4*>(&smf[r * 68 + c]);
            v.x += bb[n + 0] + tt[n + 0]; v.y += bb[n + 1] + tt[n + 1];
            v.z += bb[n + 2] + tt[n + 2]; v.w += bb[n + 3] + tt[n + 3];
            __half2 h01 = __floats2half2_rn(v.x, v.y);
            __half2 h23 = __floats2half2_rn(v.z, v.w);
            uint2 packed = make_uint2(*reinterpret_cast<uint32_t*>(&h01),
                                      *reinterpret_cast<uint32_t*>(&h23));
            *reinterpret_cast<uint2*>(&g_xwh[g][(size_t)(m0 + r) * 512 + n]) = packed;
        }
        __syncthreads();
    }
}

// ===========================================================================
// Persistent recurrence: 128 CTAs x 256 threads.
// Phase A: CTA = (m-quarter 4, n-tile 8 of width 64, gate 4); Wh fragments
//   persistent in registers; h staged in 2 K-halves overlapped with MMA;
//   xw (fp16) prefetched during previous phase B. Epilogue: g_u = cos(xw+hv).
// Phase B: CTA b scans batch row b, fast-math gates, state update.
// ===========================================================================
#define HSTR 520     // 512 + 8 pad, halves

__device__ __forceinline__ void gridbar(unsigned target) {
    __syncthreads();
    if (threadIdx.x == 0) {
        __threadfence();
        atomicAdd(&g_barrier, 1u);
        while (*((volatile unsigned*)&g_barrier) < target) { }
        __threadfence();
    }
    __syncthreads();
}

// inputs bounded (|x| <= ~3), so __expf never overflows
__device__ __forceinline__ float fsig(float x) {
    float t = __expf(-x);
    return __fdividef(1.0f, 1.0f + t);
}
__device__ __forceinline__ float ftanh(float x) {
    float t = __expf(-2.0f * x);
    return __fdividef(1.0f - t, 1.0f + t);
}

__global__ __launch_bounds__(256, 1) void recurrence_persistent(float* __restrict__ out) {
    __shared__ __align__(16) __half sH[32 * HSTR];     // 33280 B (epi float overlay)
    __shared__ __align__(16) __half sxw[32 * 64];      // 4096 B
    __shared__ float swt[8][4];

    const int tid = threadIdx.x, wid = tid >> 5, lane = tid & 31;
    const int cta = blockIdx.x;
    // Phase A mapping
    const int mq = cta & 3;
    const int nt = (cta >> 2) & 7;
    const int g  = cta >> 5;
    const int n0 = nt * 64;
    const int b0 = mq * 32;
    const int wm = wid & 1;
    const int wn = wid >> 1;
    // Phase B mapping
    const int b = cta;

    const uint32_t sH_addr  = (uint32_t)__cvta_generic_to_shared(sH);
    const uint32_t sxw_addr = (uint32_t)__cvta_generic_to_shared(sxw);

    // ---- Preload Wh fragments into registers (2 halves through sH) ----
    wmma::fragment<wmma::matrix_b, 16, 16, 16, __half, wmma::col_major> bfr[32];
#pragma unroll
    for (int half = 0; half < 2; half++) {
        __syncthreads();
#pragma unroll
        for (int it = 0; it < 8; it++) {
            int i = tid + it * 256;
            int r = i >> 6, s = i & 63;
            *reinterpret_cast<uint4*>(reinterpret_cast<char*>(sH) + (r * HSTR + s * 8) * 2) =
                *reinterpret_cast<const uint4*>(&g_Whf[g][(size_t)(n0 + half * 32 + r) * 512 + s * 8]);
        }
        __syncthreads();
        if ((wn >> 1) == half) {
            const int rloc = (wn & 1) * 16;
#pragma unroll
            for (int kk = 0; kk < 32; kk++)
                wmma::load_matrix_sync(bfr[kk], &sH[rloc * HSTR + kk * 16], HSTR);
        }
    }
    __syncthreads();

    // stage xw(t): 32 rows x 64 halves (fp16) = 256 x 16B segs
    auto stage_xw = [&](int t) {
        {
            int r = tid >> 3, s = tid & 7;
            const __half* src = &g_xwh[g][((size_t)t * BSZ + b0 + r) * 512 + n0 + s * 8];
            asm volatile("cp.async.cg.shared.global [%0], [%1], 16;"
                :: "r"(sxw_addr + (uint32_t)(r * 64 + s * 8) * 2), "l"(src) : "memory");
        }
        asm volatile("cp.async.commit_group;" ::: "memory");
    };

    stage_xw(0);

    for (int t = 0; t < T_STEPS; t++) {
        // ---- stage h tile in 2 K-halves (overlap half 1 with MMA of half 0)
#pragma unroll
        for (int half = 0; half < 2; half++) {
#pragma unroll
            for (int it = 0; it < 4; it++) {
                int i = tid + it * 256;          // 0..1023
                int r = i >> 5, s = (i & 31) + half * 32;
                const __half* src = &g_hf[(size_t)(b0 + r) * 512 + s * 8];
                asm volatile("cp.async.cg.shared.global [%0], [%1], 16;"
                    :: "r"(sH_addr + (uint32_t)(r * HSTR + s * 8) * 2), "l"(src) : "memory");
            }
            asm volatile("cp.async.commit_group;" ::: "memory");
        }

        wmma::fragment<wmma::accumulator, 16, 16, 16, float> acc;
        wmma::fill_fragment(acc, 0.0f);

        asm volatile("cp.async.wait_group 1;" ::: "memory");
        __syncthreads();
#pragma unroll
        for (int kk = 0; kk < 16; kk++) {
            wmma::fragment<wmma::matrix_a, 16, 16, 16, __half, wmma::row_major> a;
            wmma::load_matrix_sync(a, &sH[(wm * 16) * HSTR + kk * 16], HSTR);
            wmma::mma_sync(acc, a, bfr[kk], acc);
        }
        asm volatile("cp.async.wait_group 0;" ::: "memory");
        __syncthreads();
#pragma unroll
        for (int kk = 16; kk < 32; kk++) {
            wmma::fragment<wmma::matrix_a, 16, 16, 16, __half, wmma::row_major> a;
            wmma::load_matrix_sync(a, &sH[(wm * 16) * HSTR + kk * 16], HSTR);
            wmma::mma_sync(acc, a, bfr[kk], acc);
        }
        __syncthreads();   // all warps done reading sH before overlay write

        // ---- epilogue: u = cos(xw + hv)
        {
            float* smf = reinterpret_cast<float*>(sH);   // 32 x 68 overlay
            wmma::store_matrix_sync(&smf[(wm * 16) * 68 + wn * 16], acc, 68,
                                    wmma::mem_row_major);
            __syncthreads();
#pragma unroll
            for (int it = 0; it < 8; it++) {
                int i = tid + it * 256;
                int r = i >> 6, c = i & 63;
                float v = smf[r * 68 + c] + __half2float(sxw[r * 64 + c]);
                g_u[g][(size_t)(b0 + r) * 512 + n0 + c] = __cosf(v);
            }
        }
        gridbar(128u * (2u * t + 1u));

        // ---- Phase B: prefetch next xw, then scan + gates for batch row b
        if (t + 1 < T_STEPS) stage_xw(t + 1);
        {
            const int k = tid * 2;
            const int idx = b * 512 + k;
            float c0[4], c1[4], inc[4];
#pragma unroll
            for (int q = 0; q < 4; q++) {
                float2 uv = *reinterpret_cast<const float2*>(&g_u[q][idx]);
                c0[q] = uv.x; c1[q] = uv.y;
                inc[q] = c0[q] * c1[q];
            }

#pragma unroll
            for (int o = 1; o < 32; o <<= 1) {
#pragma unroll
                for (int q = 0; q < 4; q++) {
                    float up = __shfl_up_sync(0xffffffffu, inc[q], o);
                    if (lane >= o) inc[q] *= up;
                }
            }
            float exc[4];
#pragma unroll
            for (int q = 0; q < 4; q++) {
                float up = __shfl_up_sync(0xffffffffu, inc[q], 1);
                exc[q] = (lane == 0) ? 1.0f : up;
            }
            if (lane == 31) {
#pragma unroll
                for (int q = 0; q < 4; q++) swt[wid][q] = inc[q];
            }
            __syncthreads();
            float pre[4] = {1.f, 1.f, 1.f, 1.f};
            for (int w = 0; w < wid; w++) {
#pragma unroll
                for (int q = 0; q < 4; q++) pre[q] *= swt[w][q];
            }

            float P0[4], P1[4];
#pragma unroll
            for (int q = 0; q < 4; q++) {
                float e = pre[q] * exc[q];
                P0[q] = e * c0[q];
                P1[q] = P0[q] * c1[q];
            }

            float2 cold = *reinterpret_cast<const float2*>(&g_c[idx]);

            float f0 = fsig(P0[0]), f1 = fsig(P1[0]);
            float i0 = fsig(P0[1]), i1 = fsig(P1[1]);
            float u0 = ftanh(P0[2]), u1 = ftanh(P1[2]);
            float o0 = fsig(P0[3]), o1 = fsig(P1[3]);

            float cn0 = f0 * cold.x + i0 * u0;
            float cn1 = f1 * cold.y + i1 * u1;
            float h0 = o0 * ftanh(cn0);
            float h1 = o1 * ftanh(cn1);

            *reinterpret_cast<float2*>(&g_c[idx]) = make_float2(cn0, cn1);
            *reinterpret_cast<__half2*>(&g_hf[idx]) = __floats2half2_rn(h0, h1);

            *reinterpret_cast<float2*>(&out[(size_t)t * STATE_N + idx]) = make_float2(h0, h1);
            if (t == T_STEPS - 1) {
                *reinterpret_cast<float2*>(&out[OUT_MAIN + idx]) = make_float2(h0, h1);
                *reinterpret_cast<float2*>(&out[OUT_MAIN + STATE_N + idx]) = make_float2(cn0, cn1);
            }
        }
        gridbar(128u * (2u * t + 2u));
    }
}

// ===========================================================================
__global__ void init_state() {
    int i = blockIdx.x * blockDim.x + threadIdx.x;
    if (i == 0) g_barrier = 0u;
    if (i < STATE_N) {
        g_c[i] = 0.f;
        g_hf[i] = __float2half(0.f);
    }
}

extern "C" void kernel_launch(void* const* d_in, const int* in_sizes, int n_in,
                              void* d_out, int out_size) {
    const float* X = (const float*)d_in[0];
    GateParams gp;
    for (int g = 0; g < 4; g++) {
        gp.W[g]  = (const float*)d_in[1 + 3 * g];
        gp.b[g]  = (const float*)d_in[2 + 3 * g];
        gp.th[g] = (const float*)d_in[3 + 3 * g];
    }
    float* out = (float*)d_out;

    init_state<<<(STATE_N + 255) / 256, 256>>>();

    convert_x<<<(MTOT * 512 / 2) / 256, 256>>>(X);
    convert_w<<<(4 * 512 * 1024 / 2) / 256, 256>>>(gp);

    phase1_wmma<<<dim3(16, MTOT / 128), 256>>>(gp);

    recurrence_persistent<<<128, 256>>>(out);
}

// round 8
// speedup vs baseline: 3.6835x; 1.0131x over previous
#include <cuda_runtime.h>
#include <cuda_fp16.h>
#include <mma.h>
#include <math.h>
#include <stdint.h>

using namespace nvcuda;

// Problem constants
#define T_STEPS 256
#define BSZ     128
#define HID     512
#define MTOT    (T_STEPS * BSZ)                  // 32768
#define OUT_MAIN ((size_t)T_STEPS * BSZ * HID)   // 16777216
#define STATE_N  (BSZ * HID)                     // 65536

// ---------------------------------------------------------------------------
// Device scratch
// ---------------------------------------------------------------------------
__device__ __align__(256) __half g_xwh[4][(size_t)MTOT * 512];  // 128 MiB (fp16)
__device__ __align__(256) float g_u[4][STATE_N];                // cos values per step
__device__ __align__(256) float g_c[STATE_N];
__device__ __align__(256) __half g_hf[STATE_N];                 // h state, fp16

__device__ __align__(256) __half g_Xf[(size_t)MTOT * 512];
__device__ __align__(256) __half g_Wxf[4][512 * 512];
__device__ __align__(256) __half g_Whf[4][512 * 512];
__device__ __align__(256) unsigned g_bar4[4 * 32];   // one counter per quarter, 128B apart

struct GateParams {
    const float* W[4];
    const float* b[4];
    const float* th[4];
};

// ---------------------------------------------------------------------------
// Conversions
// ---------------------------------------------------------------------------
__global__ __launch_bounds__(256) void convert_x(const float* __restrict__ X) {
    size_t i = ((size_t)blockIdx.x * blockDim.x + threadIdx.x) * 2;
    float2 v = *reinterpret_cast<const float2*>(X + i);
    *reinterpret_cast<__half2*>(&g_Xf[i]) = __floats2half2_rn(v.x, v.y);
}

__global__ __launch_bounds__(256) void convert_w(GateParams gp) {
    size_t i = ((size_t)blockIdx.x * blockDim.x + threadIdx.x) * 2;
    int g = (int)(i >> 19);
    size_t r = i & 524287;
    int n = (int)(r >> 10), k = (int)(r & 1023);
    float2 v = *reinterpret_cast<const float2*>(gp.W[g] + (size_t)n * 1024 + k);
    __half2 h = __floats2half2_rn(v.x, v.y);
    if (k < 512)
        *reinterpret_cast<__half2*>(&g_Wxf[g][(size_t)n * 512 + k]) = h;
    else
        *reinterpret_cast<__half2*>(&g_Whf[g][(size_t)n * 512 + (k - 512)]) = h;
}

// ===========================================================================
// Phase 1: fp16 WMMA, 4-stage cp.async pipeline (depth 3 in flight).
// CTA 128(m) x 128(n); 8 warps = 4(m) x 2(n). Dynamic smem 4 x 20480 B.
// ===========================================================================
#define SSTR1 40
#define P1_STAGE 20480

__global__ __launch_bounds__(256) void phase1_wmma(GateParams gp) {
    extern __shared__ __align__(16) char smraw[];

    const int tid = threadIdx.x, wid = tid >> 5;
    const int nt = blockIdx.x;
    const int g  = nt >> 2;
    const int n0 = (nt & 3) * 128;
    const int m0 = blockIdx.y * 128;
    const int wm = wid >> 1;
    const int wn = wid & 1;

    const uint32_t smaddr = (uint32_t)__cvta_generic_to_shared(smraw);

    auto stage = [&](int c) {
        const int k0 = c * 32;
        const uint32_t base = smaddr + (uint32_t)(c & 3) * P1_STAGE;
#pragma unroll
        for (int it = 0; it < 4; it++) {
            int i = tid + it * 256;
            int mat = i >> 9;
            int r = (i >> 2) & 127, s = i & 3;
            const __half* src = mat
                ? &g_Wxf[g][(size_t)(n0 + r) * 512 + k0 + s * 8]
                : &g_Xf[(size_t)(m0 + r) * 512 + k0 + s * 8];
            asm volatile("cp.async.cg.shared.global [%0], [%1], 16;"
                :: "r"(base + (uint32_t)mat * 10240 + (uint32_t)(r * SSTR1 + s * 8) * 2),
                   "l"(src) : "memory");
        }
        asm volatile("cp.async.commit_group;" ::: "memory");
    };

    wmma::fragment<wmma::accumulator, 16, 16, 16, float> acc[2][4];
#pragma unroll
    for (int i = 0; i < 2; i++)
#pragma unroll
        for (int j = 0; j < 4; j++) wmma::fill_fragment(acc[i][j], 0.0f);

    stage(0); stage(1); stage(2);
    for (int c = 0; c < 16; c++) {
        if (c < 13) {
            stage(c + 3);
            asm volatile("cp.async.wait_group 3;" ::: "memory");
        } else if (c == 13) {
            asm volatile("cp.async.wait_group 2;" ::: "memory");
        } else if (c == 14) {
            asm volatile("cp.async.wait_group 1;" ::: "memory");
        } else {
            asm volatile("cp.async.wait_group 0;" ::: "memory");
        }
        __syncthreads();
        const __half* sA = reinterpret_cast<const __half*>(smraw + (c & 3) * P1_STAGE);
        const __half* sB = sA + 128 * SSTR1;
#pragma unroll
        for (int kk = 0; kk < 32; kk += 16) {
            wmma::fragment<wmma::matrix_a, 16, 16, 16, __half, wmma::row_major> a[2];
            wmma::fragment<wmma::matrix_b, 16, 16, 16, __half, wmma::col_major> bfr[4];
#pragma unroll
            for (int i = 0; i < 2; i++)
                wmma::load_matrix_sync(a[i], &sA[(wm * 32 + i * 16) * SSTR1 + kk], SSTR1);
#pragma unroll
            for (int j = 0; j < 4; j++)
                wmma::load_matrix_sync(bfr[j], &sB[(wn * 64 + j * 16) * SSTR1 + kk], SSTR1);
#pragma unroll
            for (int i = 0; i < 2; i++)
#pragma unroll
                for (int j = 0; j < 4; j++)
                    wmma::mma_sync(acc[i][j], a[i], bfr[j], acc[i][j]);
        }
        __syncthreads();
    }

    float* smf = reinterpret_cast<float*>(smraw);
    const float* __restrict__ bb = gp.b[g];
    const float* __restrict__ tt = gp.th[g];
#pragma unroll
    for (int half = 0; half < 2; half++) {
        if (wn == half) {
#pragma unroll
            for (int i = 0; i < 2; i++)
#pragma unroll
                for (int j = 0; j < 4; j++)
                    wmma::store_matrix_sync(&smf[(wm * 32 + i * 16) * 68 + j * 16],
                                            acc[i][j], 68, wmma::mem_row_major);
        }
        __syncthreads();
#pragma unroll
        for (int it = 0; it < 8; it++) {
            int i = tid + it * 256;
            int r = i >> 4, c = (i & 15) * 4;
            int n = n0 + half * 64 + c;
            float4 v = *reinterpret_cast<const float4*>(&smf[r * 68 + c]);
            v.x += bb[n + 0] + tt[n + 0]; v.y += bb[n + 1] + tt[n + 1];
            v.z += bb[n + 2] + tt[n + 2]; v.w += bb[n + 3] + tt[n + 3];
            __half2 h01 = __floats2half2_rn(v.x, v.y);
            __half2 h23 = __floats2half2_rn(v.z, v.w);
            uint2 packed = make_uint2(*reinterpret_cast<uint32_t*>(&h01),
                                      *reinterpret_cast<uint32_t*>(&h23));
            *reinterpret_cast<uint2*>(&g_xwh[g][(size_t)(m0 + r) * 512 + n]) = packed;
        }
        __syncthreads();
    }
}

// ===========================================================================
// Persistent recurrence: 128 CTAs x 256 threads, quarter-local barriers.
// Quarter q = cta>>5 owns batch rows [q*32, q*32+32) for BOTH phases.
// Phase A: within-quarter index -> (gate 4, n-tile 8 of width 64); Wh frags
//   in registers; h staged in 2 K-halves overlapped with dual-acc MMA.
// Phase B: CTA b scans batch row b, fast-math gates, state update.
// ===========================================================================
#define HSTR 520     // 512 + 8 pad, halves

__device__ __forceinline__ void quarterbar(int q, unsigned target) {
    __syncthreads();
    if (threadIdx.x == 0) {
        __threadfence();
        atomicAdd(&g_bar4[q * 32], 1u);
        while (*((volatile unsigned*)&g_bar4[q * 32]) < target) { }
        __threadfence();
    }
    __syncthreads();
}

// inputs bounded (|x| <= ~3), so __expf never overflows
__device__ __forceinline__ float fsig(float x) {
    float t = __expf(-x);
    return __fdividef(1.0f, 1.0f + t);
}
__device__ __forceinline__ float ftanh(float x) {
    float t = __expf(-2.0f * x);
    return __fdividef(1.0f - t, 1.0f + t);
}

__global__ __launch_bounds__(256, 1) void recurrence_persistent(float* __restrict__ out) {
    __shared__ __align__(16) __half sH[32 * HSTR];     // 33280 B (epi float overlay)
    __shared__ __align__(16) __half sxw[32 * 64];      // 4096 B
    __shared__ float swt[8][4];

    const int tid = threadIdx.x, wid = tid >> 5, lane = tid & 31;
    const int cta = blockIdx.x;
    const int q   = cta >> 5;                // quarter for BOTH phases
    const int within = cta & 31;
    // Phase A mapping
    const int g  = within >> 3;
    const int nt = within & 7;
    const int n0 = nt * 64;
    const int b0 = q * 32;
    const int wm = wid & 1;
    const int wn = wid >> 1;
    // Phase B mapping
    const int b = cta;

    const uint32_t sH_addr  = (uint32_t)__cvta_generic_to_shared(sH);
    const uint32_t sxw_addr = (uint32_t)__cvta_generic_to_shared(sxw);

    // ---- Preload Wh fragments into registers (2 halves through sH) ----
    wmma::fragment<wmma::matrix_b, 16, 16, 16, __half, wmma::col_major> bfr[32];
#pragma unroll
    for (int half = 0; half < 2; half++) {
        __syncthreads();
#pragma unroll
        for (int it = 0; it < 8; it++) {
            int i = tid + it * 256;
            int r = i >> 6, s = i & 63;
            *reinterpret_cast<uint4*>(reinterpret_cast<char*>(sH) + (r * HSTR + s * 8) * 2) =
                *reinterpret_cast<const uint4*>(&g_Whf[g][(size_t)(n0 + half * 32 + r) * 512 + s * 8]);
        }
        __syncthreads();
        if ((wn >> 1) == half) {
            const int rloc = (wn & 1) * 16;
#pragma unroll
            for (int kk = 0; kk < 32; kk++)
                wmma::load_matrix_sync(bfr[kk], &sH[rloc * HSTR + kk * 16], HSTR);
        }
    }
    __syncthreads();

    // stage xw(t): 32 rows x 64 halves (fp16) = 256 x 16B segs
    auto stage_xw = [&](int t) {
        {
            int r = tid >> 3, s = tid & 7;
            const __half* src = &g_xwh[g][((size_t)t * BSZ + b0 + r) * 512 + n0 + s * 8];
            asm volatile("cp.async.cg.shared.global [%0], [%1], 16;"
                :: "r"(sxw_addr + (uint32_t)(r * 64 + s * 8) * 2), "l"(src) : "memory");
        }
        asm volatile("cp.async.commit_group;" ::: "memory");
    };

    stage_xw(0);

    for (int t = 0; t < T_STEPS; t++) {
        // ---- stage h tile in 2 K-halves (overlap half 1 with MMA of half 0)
#pragma unroll
        for (int half = 0; half < 2; half++) {
#pragma unroll
            for (int it = 0; it < 4; it++) {
                int i = tid + it * 256;          // 0..1023
                int r = i >> 5, s = (i & 31) + half * 32;
                const __half* src = &g_hf[(size_t)(b0 + r) * 512 + s * 8];
                asm volatile("cp.async.cg.shared.global [%0], [%1], 16;"
                    :: "r"(sH_addr + (uint32_t)(r * HSTR + s * 8) * 2), "l"(src) : "memory");
            }
            asm volatile("cp.async.commit_group;" ::: "memory");
        }

        wmma::fragment<wmma::accumulator, 16, 16, 16, float> acc0, acc1;
        wmma::fill_fragment(acc0, 0.0f);
        wmma::fill_fragment(acc1, 0.0f);

        asm volatile("cp.async.wait_group 1;" ::: "memory");
        __syncthreads();
#pragma unroll
        for (int kk = 0; kk < 16; kk += 2) {
            wmma::fragment<wmma::matrix_a, 16, 16, 16, __half, wmma::row_major> a0, a1;
            wmma::load_matrix_sync(a0, &sH[(wm * 16) * HSTR + kk * 16], HSTR);
            wmma::load_matrix_sync(a1, &sH[(wm * 16) * HSTR + (kk + 1) * 16], HSTR);
            wmma::mma_sync(acc0, a0, bfr[kk], acc0);
            wmma::mma_sync(acc1, a1, bfr[kk + 1], acc1);
        }
        asm volatile("cp.async.wait_group 0;" ::: "memory");
        __syncthreads();
#pragma unroll
        for (int kk = 16; kk < 32; kk += 2) {
            wmma::fragment<wmma::matrix_a, 16, 16, 16, __half, wmma::row_major> a0, a1;
            wmma::load_matrix_sync(a0, &sH[(wm * 16) * HSTR + kk * 16], HSTR);
            wmma::load_matrix_sync(a1, &sH[(wm * 16) * HSTR + (kk + 1) * 16], HSTR);
            wmma::mma_sync(acc0, a0, bfr[kk], acc0);
            wmma::mma_sync(acc1, a1, bfr[kk + 1], acc1);
        }
#pragma unroll
        for (int e = 0; e < acc0.num_elements; e++) acc0.x[e] += acc1.x[e];
        __syncthreads();   // all warps done reading sH before overlay write

        // ---- epilogue: u = cos(xw + hv)
        {
            float* smf = reinterpret_cast<float*>(sH);   // 32 x 68 overlay
            wmma::store_matrix_sync(&smf[(wm * 16) * 68 + wn * 16], acc0, 68,
                                    wmma::mem_row_major);
            __syncthreads();
#pragma unroll
            for (int it = 0; it < 8; it++) {
                int i = tid + it * 256;
                int r = i >> 6, c = i & 63;
                float v = smf[r * 68 + c] + __half2float(sxw[r * 64 + c]);
                g_u[g][(size_t)(b0 + r) * 512 + n0 + c] = __cosf(v);
            }
        }
        quarterbar(q, 32u * (2u * t + 1u));

        // ---- Phase B: prefetch next xw, then scan + gates for batch row b
        if (t + 1 < T_STEPS) stage_xw(t + 1);
        {
            const int k = tid * 2;
            const int idx = b * 512 + k;
            float c0[4], c1[4], inc[4];
#pragma unroll
            for (int qq = 0; qq < 4; qq++) {
                float2 uv = *reinterpret_cast<const float2*>(&g_u[qq][idx]);
                c0[qq] = uv.x; c1[qq] = uv.y;
                inc[qq] = c0[qq] * c1[qq];
            }

#pragma unroll
            for (int o = 1; o < 32; o <<= 1) {
#pragma unroll
                for (int qq = 0; qq < 4; qq++) {
                    float up = __shfl_up_sync(0xffffffffu, inc[qq], o);
                    if (lane >= o) inc[qq] *= up;
                }
            }
            float exc[4];
#pragma unroll
            for (int qq = 0; qq < 4; qq++) {
                float up = __shfl_up_sync(0xffffffffu, inc[qq], 1);
                exc[qq] = (lane == 0) ? 1.0f : up;
            }
            if (lane == 31) {
#pragma unroll
                for (int qq = 0; qq < 4; qq++) swt[wid][qq] = inc[qq];
            }
            __syncthreads();
            float pre[4] = {1.f, 1.f, 1.f, 1.f};
            for (int w = 0; w < wid; w++) {
#pragma unroll
                for (int qq = 0; qq < 4; qq++) pre[qq] *= swt[w][qq];
            }

            float P0[4], P1[4];
#pragma unroll
            for (int qq = 0; qq < 4; qq++) {
                float e = pre[qq] * exc[qq];
                P0[qq] = e * c0[qq];
                P1[qq] = P0[qq] * c1[qq];
            }

            float2 cold = *reinterpret_cast<const float2*>(&g_c[idx]);

            float f0 = fsig(P0[0]), f1 = fsig(P1[0]);
            float i0 = fsig(P0[1]), i1 = fsig(P1[1]);
            float u0 = ftanh(P0[2]), u1 = ftanh(P1[2]);
            float o0 = fsig(P0[3]), o1 = fsig(P1[3]);

            float cn0 = f0 * cold.x + i0 * u0;
            float cn1 = f1 * cold.y + i1 * u1;
            float h0 = o0 * ftanh(cn0);
            float h1 = o1 * ftanh(cn1);

            *reinterpret_cast<float2*>(&g_c[idx]) = make_float2(cn0, cn1);
            *reinterpret_cast<__half2*>(&g_hf[idx]) = __floats2half2_rn(h0, h1);

            *reinterpret_cast<float2*>(&out[(size_t)t * STATE_N + idx]) = make_float2(h0, h1);
            if (t == T_STEPS - 1) {
                *reinterpret_cast<float2*>(&out[OUT_MAIN + idx]) = make_float2(h0, h1);
                *reinterpret_cast<float2*>(&out[OUT_MAIN + STATE_N + idx]) = make_float2(cn0, cn1);
            }
        }
        quarterbar(q, 32u * (2u * t + 2u));
    }
}

// ===========================================================================
__global__ void init_state() {
    int i = blockIdx.x * blockDim.x + threadIdx.x;
    if (i < 4 * 32) g_bar4[i] = 0u;
    if (i < STATE_N) {
        g_c[i] = 0.f;
        g_hf[i] = __float2half(0.f);
    }
}

extern "C" void kernel_launch(void* const* d_in, const int* in_sizes, int n_in,
                              void* d_out, int out_size) {
    const float* X = (const float*)d_in[0];
    GateParams gp;
    for (int g = 0; g < 4; g++) {
        gp.W[g]  = (const float*)d_in[1 + 3 * g];
        gp.b[g]  = (const float*)d_in[2 + 3 * g];
        gp.th[g] = (const float*)d_in[3 + 3 * g];
    }
    float* out = (float*)d_out;

    init_state<<<(STATE_N + 255) / 256, 256>>>();

    convert_x<<<(MTOT * 512 / 2) / 256, 256>>>(X);
    convert_w<<<(4 * 512 * 1024 / 2) / 256, 256>>>(gp);

    const int p1_smem = 4 * P1_STAGE;   // 81920
    cudaFuncSetAttribute(phase1_wmma, cudaFuncAttributeMaxDynamicSharedMemorySize,
                         p1_smem);
    phase1_wmma<<<dim3(16, MTOT / 128), 256, p1_smem>>>(gp);

    recurrence_persistent<<<128, 256>>>(out);
}